// round 15
// baseline (speedup 1.0000x reference)
#include <cuda_runtime.h>
#include <cuda_bf16.h>
#include <cstdint>

// ---------------- problem constants (fixed for this dataset) ----------------
#define D_    128
#define DA_   64
#define DB_   8
#define NR_   6
#define NS_   42
#define E_MAX 200000
#define T_MAX 1600000
#define RT_MAX 12504            // row-tiles of 16

// ---------------- scratch (static device globals; no allocation) ------------
__device__ __align__(16) uint4 g_fX  [(size_t)2 * RT_MAX * 8 * 32];
__device__ __align__(16) float g_down[(size_t)E_MAX * DA_];
__device__ __align__(16) float g_agg [(size_t)E_MAX * DA_];
__device__ __align__(16) float g_wcomb[NR_ * D_];
__device__ __align__(16) float g_hsbf[(size_t)T_MAX * DB_];
__device__ __align__(16) uint32_t g_wfrag[163840];

#define OFF_Wkj    0
#define OFF_Wji    16384
#define OFF_rb1W1  32768
#define OFF_rb1W2  49152
#define OFF_Wfin   65536
#define OFF_ra1W1  81920
#define OFF_ra1W2  98304
#define OFF_ra2W1  114688
#define OFF_ra2W2  131072
#define OFF_Wdown  147456
#define OFF_Wup    155648

// ---------------- helpers ----------------------------------------------------
__device__ __forceinline__ float silu_f(float x) {
    return x / (1.0f + __expf(-x));
}
__device__ __forceinline__ void splitpack2(float x0, float x1,
                                           uint32_t& hi, uint32_t& lo) {
    asm("cvt.rn.bf16x2.f32 %0, %1, %2;" : "=r"(hi) : "f"(x1), "f"(x0));
    float f0 = __uint_as_float(hi << 16);
    float f1 = __uint_as_float(hi & 0xFFFF0000u);
    float l0 = x0 - f0;
    float l1 = x1 - f1;
    asm("cvt.rn.bf16x2.f32 %0, %1, %2;" : "=r"(lo) : "f"(l1), "f"(l0));
}
__device__ __forceinline__ float lo16f(uint32_t u) { return __uint_as_float(u << 16); }
__device__ __forceinline__ float hi16f(uint32_t u) { return __uint_as_float(u & 0xFFFF0000u); }

__device__ __forceinline__ void mma_bf16(float* c, const uint32_t* a, const uint32_t* b) {
    asm volatile(
        "mma.sync.aligned.m16n8k16.row.col.f32.bf16.bf16.f32 "
        "{%0,%1,%2,%3}, {%4,%5,%6,%7}, {%8,%9}, {%0,%1,%2,%3};"
        : "+f"(c[0]), "+f"(c[1]), "+f"(c[2]), "+f"(c[3])
        : "r"(a[0]), "r"(a[1]), "r"(a[2]), "r"(a[3]), "r"(b[0]), "r"(b[1]));
}
__device__ __forceinline__ void cp_async16(uint32_t saddr, const void* gaddr) {
    asm volatile("cp.async.cg.shared.global [%0], [%1], 16;"
                 :: "r"(saddr), "l"(gaddr));
}
#define CP_COMMIT() asm volatile("cp.async.commit_group;" ::: "memory")
#define CP_WAIT(n)  asm volatile("cp.async.wait_group %0;" :: "n"(n) : "memory")
__device__ __forceinline__ uint32_t smem_u32(const void* p) {
    uint32_t a;
    asm("{ .reg .u64 t; cvta.to.shared.u64 t, %1; cvt.u32.u64 %0, t; }" : "=r"(a) : "l"(p));
    return a;
}

// ---------------- fused HEAD chain: Wkj -> Wdown -> Wji, 64 rows/CTA -----------
// (byte-identical to validated R14 version)
#define HSM_BIAS 0                      // bkj[128], bji[128]
#define HSM_WC   1024                   // wcomb 6x128
#define HSM_M    4096                   // 32768: m_input frags
#define HSM_P    (HSM_M + 32768)        // 32768: Wkj output frags
#define HSM_BS   (HSM_P + 32768)        // 4 x 8192 B ring
#define HSM_TOTAL (HSM_BS + 32768)      // 102400

__global__ void __launch_bounds__(256, 2) head_chain(
    const float* __restrict__ m_input, const float* __restrict__ rbf,
    const uint32_t* __restrict__ wf,
    const float* __restrict__ bkj, const float* __restrict__ bji,
    const float* __restrict__ wcombG,
    float* __restrict__ down,
    uint4* __restrict__ fXH, uint4* __restrict__ fXL, int E)
{
    extern __shared__ char smem[];
    const uint32_t sb = smem_u32(smem);
    const int tid = threadIdx.x, lane = tid & 31, wid = tid >> 5;
    const int warpM = wid >> 2, warpN = wid & 3;
    const int rt0 = blockIdx.x * 4;                 // 64 rows per CTA

    if (tid < 128) {
        ((float*)(smem + HSM_BIAS))[tid]       = bkj[tid];
        ((float*)(smem + HSM_BIAS))[128 + tid] = bji[tid];
    }
    for (int i = tid; i < NR_ * D_; i += 256)
        ((float*)(smem + HSM_WC))[i] = wcombG[i];

    // ---- A preload + split (once) into M ----
#pragma unroll
    for (int i = 0; i < 4; i++) {
        int f = tid + i * 256;
        int ln = f & 31, gm = (f >> 5) & 3, s = f >> 7;
        int r0 = rt0 * 16 + gm * 16 + (ln >> 2);
        int k0 = s * 16 + 2 * (ln & 3);
        int rA = (r0     < E) ? r0     : E - 1;
        int rB = (r0 + 8 < E) ? r0 + 8 : E - 1;
        const float* bA = m_input + (size_t)rA * D_ + k0;
        const float* bB = m_input + (size_t)rB * D_ + k0;
        float2 v0 = *(const float2*)bA;
        float2 v1 = *(const float2*)bB;
        float2 v2 = *(const float2*)(bA + 8);
        float2 v3 = *(const float2*)(bB + 8);
        uint4 h, l;
        splitpack2(v0.x, v0.y, h.x, l.x);
        splitpack2(v1.x, v1.y, h.y, l.y);
        splitpack2(v2.x, v2.y, h.z, l.z);
        splitpack2(v3.x, v3.y, h.w, l.w);
        *(uint4*)(smem + HSM_M + (((s * 2 + 0) * 4 + gm) * 32 + ln) * 16) = h;
        *(uint4*)(smem + HSM_M + (((s * 2 + 1) * 4 + gm) * 32 + ln) * 16) = l;
    }

    float acc[2][4][4];

    auto prefB = [&](const uint32_t* wfb, int s, int nq4) {
#pragma unroll
        for (int i = 0; i < 2; i++) {
            int f = tid + i * 256;
            if (f < nq4)
                cp_async16(sb + HSM_BS + (s & 3) * 8192 + f * 16,
                           (const uint4*)wfb + s * nq4 + f);
        }
    };
    auto compute128 = [&](int aOff, int s) {
        const char* ab = smem + aOff;
        uint4 ahi[2], alo[2];
#pragma unroll
        for (int mt = 0; mt < 2; mt++) {
            int gm = warpM * 2 + mt;
            ahi[mt] = *(const uint4*)(ab + (((s * 2 + 0) * 4 + gm) * 32 + lane) * 16);
            alo[mt] = *(const uint4*)(ab + (((s * 2 + 1) * 4 + gm) * 32 + lane) * 16);
        }
#pragma unroll
        for (int nt = 0; nt < 4; nt++) {
            int gt = warpN * 4 + nt;
            uint4 bq = *(const uint4*)(smem + HSM_BS + (s & 3) * 8192 + (gt * 32 + lane) * 16);
            uint32_t bh[2] = {bq.x, bq.y};
            uint32_t bl[2] = {bq.z, bq.w};
#pragma unroll
            for (int mt = 0; mt < 2; mt++) {
                mma_bf16(acc[mt][nt], (const uint32_t*)&ahi[mt], bh);
                mma_bf16(acc[mt][nt], (const uint32_t*)&ahi[mt], bl);
                mma_bf16(acc[mt][nt], (const uint32_t*)&alo[mt], bh);
            }
        }
    };
    auto runstage128 = [&](int aOff, const uint32_t* wfb) {
#pragma unroll
        for (int mt = 0; mt < 2; mt++)
#pragma unroll
            for (int nt = 0; nt < 4; nt++)
#pragma unroll
                for (int j = 0; j < 4; j++) acc[mt][nt][j] = 0.f;
        prefB(wfb, 0, 512); CP_COMMIT();
        prefB(wfb, 1, 512); CP_COMMIT();
        for (int s = 0; s < 8; s++) {
            if (s + 2 < 8) { prefB(wfb, s + 2, 512); CP_COMMIT(); }
            if (s + 2 < 8)      CP_WAIT(2);
            else if (s + 1 < 8) CP_WAIT(1);
            else                CP_WAIT(0);
            __syncthreads();
            compute128(aOff, s);
        }
    };

    // ================= S0: Wkj (A=M) -> P, epi silu(+bkj) * rbfmod ============
    runstage128(HSM_M, wf + OFF_Wkj);
    {
        float* sBk = (float*)(smem + HSM_BIAS);
        float* sWc = (float*)(smem + HSM_WC);
#pragma unroll
        for (int mt = 0; mt < 2; mt++) {
            const int rtg = rt0 + warpM * 2 + mt;
            const int gm  = warpM * 2 + mt;
            float o[4][4];
#pragma unroll
            for (int nt = 0; nt < 4; nt++) {
                int col = warpN * 32 + nt * 8 + 2 * (lane & 3);
#pragma unroll
                for (int half = 0; half < 2; half++) {
                    o[nt][half * 2 + 0] = silu_f(acc[mt][nt][half * 2 + 0] + sBk[col]);
                    o[nt][half * 2 + 1] = silu_f(acc[mt][nt][half * 2 + 1] + sBk[col + 1]);
                }
            }
            int rA = rtg * 16 + (lane >> 2);
            int rB = rA + 8;
            if (rA >= E) rA = E - 1;
            if (rB >= E) rB = E - 1;
            const float* pa = rbf + (size_t)rA * NR_;
            const float* pb = rbf + (size_t)rB * NR_;
            float2 a0 = __ldg((const float2*)pa), a1 = __ldg((const float2*)pa + 1),
                   a2 = __ldg((const float2*)pa + 2);
            float2 b0 = __ldg((const float2*)pb), b1 = __ldg((const float2*)pb + 1),
                   b2 = __ldg((const float2*)pb + 2);
            float hA[6] = {a0.x, a0.y, a1.x, a1.y, a2.x, a2.y};
            float hB[6] = {b0.x, b0.y, b1.x, b1.y, b2.x, b2.y};
#pragma unroll
            for (int nt = 0; nt < 4; nt++) {
                int col = warpN * 32 + nt * 8 + 2 * (lane & 3);
                float r0 = 0.f, r1 = 0.f, r2 = 0.f, r3 = 0.f;
#pragma unroll
                for (int j = 0; j < NR_; j++) {
                    float w0 = sWc[j * D_ + col], w1 = sWc[j * D_ + col + 1];
                    r0 += hA[j] * w0; r1 += hA[j] * w1;
                    r2 += hB[j] * w0; r3 += hB[j] * w1;
                }
                o[nt][0] *= r0; o[nt][1] *= r1; o[nt][2] *= r2; o[nt][3] *= r3;
            }
#pragma unroll
            for (int j = 0; j < 2; j++) {
                uint4 h, l;
                splitpack2(o[2 * j][0],     o[2 * j][1],     h.x, l.x);
                splitpack2(o[2 * j][2],     o[2 * j][3],     h.y, l.y);
                splitpack2(o[2 * j + 1][0], o[2 * j + 1][1], h.z, l.z);
                splitpack2(o[2 * j + 1][2], o[2 * j + 1][3], h.w, l.w);
                int sp = warpN * 2 + j;
                *(uint4*)(smem + HSM_P + (((sp * 2 + 0) * 4 + gm) * 32 + lane) * 16) = h;
                *(uint4*)(smem + HSM_P + (((sp * 2 + 1) * 4 + gm) * 32 + lane) * 16) = l;
            }
        }
    }

    // ================= S1: Wdown (A=P, NT=64) -> down fp32 global =============
    {
        const int gm4 = wid >> 1;       // 0..3 (16 rows each)
        const int wn2 = wid & 1;        // 0..1 (32 cols each)
        float a1acc[4][4];
#pragma unroll
        for (int nt = 0; nt < 4; nt++)
#pragma unroll
            for (int j = 0; j < 4; j++) a1acc[nt][j] = 0.f;
        const uint32_t* wfb = wf + OFF_Wdown;
        prefB(wfb, 0, 256); CP_COMMIT();
        prefB(wfb, 1, 256); CP_COMMIT();
        for (int s = 0; s < 8; s++) {
            if (s + 2 < 8) { prefB(wfb, s + 2, 256); CP_COMMIT(); }
            if (s + 2 < 8)      CP_WAIT(2);
            else if (s + 1 < 8) CP_WAIT(1);
            else                CP_WAIT(0);
            __syncthreads();
            const char* ab = smem + HSM_P;
            uint4 ahi = *(const uint4*)(ab + (((s * 2 + 0) * 4 + gm4) * 32 + lane) * 16);
            uint4 alo = *(const uint4*)(ab + (((s * 2 + 1) * 4 + gm4) * 32 + lane) * 16);
#pragma unroll
            for (int nt = 0; nt < 4; nt++) {
                int gt = wn2 * 4 + nt;
                uint4 bq = *(const uint4*)(smem + HSM_BS + (s & 3) * 8192 + (gt * 32 + lane) * 16);
                uint32_t bh[2] = {bq.x, bq.y};
                uint32_t bl[2] = {bq.z, bq.w};
                mma_bf16(a1acc[nt], (const uint32_t*)&ahi, bh);
                mma_bf16(a1acc[nt], (const uint32_t*)&ahi, bl);
                mma_bf16(a1acc[nt], (const uint32_t*)&alo, bh);
            }
        }
        const int rtg = rt0 + gm4;
#pragma unroll
        for (int nt = 0; nt < 4; nt++) {
            int col = wn2 * 32 + nt * 8 + 2 * (lane & 3);
#pragma unroll
            for (int half = 0; half < 2; half++) {
                int row = rtg * 16 + (lane >> 2) + half * 8;
                if (row < E)
                    *(float2*)(down + (size_t)row * DA_ + col) =
                        make_float2(silu_f(a1acc[nt][half * 2 + 0]),
                                    silu_f(a1acc[nt][half * 2 + 1]));
            }
        }
    }

    // ================= S2: Wji (A=M) -> fX frag global, epi silu(+bji) ========
    runstage128(HSM_M, wf + OFF_Wji);
    {
        float* sBj = (float*)(smem + HSM_BIAS) + 128;
#pragma unroll
        for (int mt = 0; mt < 2; mt++) {
            const int rtg = rt0 + warpM * 2 + mt;
            float o[4][4];
#pragma unroll
            for (int nt = 0; nt < 4; nt++) {
                int col = warpN * 32 + nt * 8 + 2 * (lane & 3);
#pragma unroll
                for (int half = 0; half < 2; half++) {
                    o[nt][half * 2 + 0] = silu_f(acc[mt][nt][half * 2 + 0] + sBj[col]);
                    o[nt][half * 2 + 1] = silu_f(acc[mt][nt][half * 2 + 1] + sBj[col + 1]);
                }
            }
#pragma unroll
            for (int j = 0; j < 2; j++) {
                uint4 h, l;
                splitpack2(o[2 * j][0],     o[2 * j][1],     h.x, l.x);
                splitpack2(o[2 * j][2],     o[2 * j][3],     h.y, l.y);
                splitpack2(o[2 * j + 1][0], o[2 * j + 1][1], h.z, l.z);
                splitpack2(o[2 * j + 1][2], o[2 * j + 1][3], h.w, l.w);
                int q = (rtg * 8 + warpN * 2 + j) * 32 + lane;
                fXH[q] = h;
                fXL[q] = l;
            }
        }
    }
}

// ---------------- fused 8-GEMM TAIL chain: 6-slab B ring, 2 steps/sync ---------
#define RES_NONE 0
#define RES_SMEM 1
#define RES_GFR  2
#define RES_F32  3

#define TSM_P    0
#define TSM_Q    32768
#define TSM_BS   65536                 // 6 x 8192 ring
#define TSM_TOTAL 114688

template<int RES, bool OUTG>
__device__ __forceinline__ void epi_stage64(
    char* smem, float (&acc)[2][4][4], const float* gBias,
    int resOff, const uint4* gResH, const uint4* gResL, const float* resF,
    int outOff, float* outF,
    int lane, int warpM, int warpN, int rt0, int E)
{
#pragma unroll
    for (int mt = 0; mt < 2; mt++) {
        const int rtg = rt0 + warpM * 2 + mt;
        const int gm  = warpM * 2 + mt;
        float o[4][4];
#pragma unroll
        for (int nt = 0; nt < 4; nt++) {
            int col = warpN * 32 + nt * 8 + 2 * (lane & 3);
            float b0 = gBias ? __ldg(gBias + col)     : 0.f;
            float b1 = gBias ? __ldg(gBias + col + 1) : 0.f;
#pragma unroll
            for (int half = 0; half < 2; half++) {
                o[nt][half * 2 + 0] = silu_f(acc[mt][nt][half * 2 + 0] + b0);
                o[nt][half * 2 + 1] = silu_f(acc[mt][nt][half * 2 + 1] + b1);
            }
        }
        if (RES == RES_SMEM || RES == RES_GFR) {
#pragma unroll
            for (int j = 0; j < 2; j++) {
                uint4 rh, rl;
                int sp = warpN * 2 + j;
                if (RES == RES_SMEM) {
                    rh = *(const uint4*)(smem + resOff + (((sp * 2 + 0) * 4 + gm) * 32 + lane) * 16);
                    rl = *(const uint4*)(smem + resOff + (((sp * 2 + 1) * 4 + gm) * 32 + lane) * 16);
                } else {
                    int q = (rtg * 8 + sp) * 32 + lane;
                    rh = __ldg(gResH + q);
                    rl = __ldg(gResL + q);
                }
                o[2 * j    ][0] += lo16f(rh.x) + lo16f(rl.x);
                o[2 * j    ][1] += hi16f(rh.x) + hi16f(rl.x);
                o[2 * j    ][2] += lo16f(rh.y) + lo16f(rl.y);
                o[2 * j    ][3] += hi16f(rh.y) + hi16f(rl.y);
                o[2 * j + 1][0] += lo16f(rh.z) + lo16f(rl.z);
                o[2 * j + 1][1] += hi16f(rh.z) + hi16f(rl.z);
                o[2 * j + 1][2] += lo16f(rh.w) + lo16f(rl.w);
                o[2 * j + 1][3] += hi16f(rh.w) + hi16f(rl.w);
            }
        } else if (RES == RES_F32) {
#pragma unroll
            for (int nt = 0; nt < 4; nt++) {
                int col = warpN * 32 + nt * 8 + 2 * (lane & 3);
#pragma unroll
                for (int half = 0; half < 2; half++) {
                    int row = rtg * 16 + (lane >> 2) + half * 8;
                    if (row >= E) row = E - 1;
                    float2 rr = __ldg((const float2*)(resF + (size_t)row * D_ + col));
                    o[nt][half * 2 + 0] += rr.x;
                    o[nt][half * 2 + 1] += rr.y;
                }
            }
        }
        if (OUTG) {
#pragma unroll
            for (int nt = 0; nt < 4; nt++) {
                int col = warpN * 32 + nt * 8 + 2 * (lane & 3);
#pragma unroll
                for (int half = 0; half < 2; half++) {
                    int row = rtg * 16 + (lane >> 2) + half * 8;
                    if (row < E)
                        *(float2*)(outF + (size_t)row * D_ + col) =
                            make_float2(o[nt][half * 2], o[nt][half * 2 + 1]);
                }
            }
        } else {
#pragma unroll
            for (int j = 0; j < 2; j++) {
                uint4 h, l;
                splitpack2(o[2 * j][0],     o[2 * j][1],     h.x, l.x);
                splitpack2(o[2 * j][2],     o[2 * j][3],     h.y, l.y);
                splitpack2(o[2 * j + 1][0], o[2 * j + 1][1], h.z, l.z);
                splitpack2(o[2 * j + 1][2], o[2 * j + 1][3], h.w, l.w);
                int sp = warpN * 2 + j;
                *(uint4*)(smem + outOff + (((sp * 2 + 0) * 4 + gm) * 32 + lane) * 16) = h;
                *(uint4*)(smem + outOff + (((sp * 2 + 1) * 4 + gm) * 32 + lane) * 16) = l;
            }
        }
    }
}

__global__ void __launch_bounds__(256, 2) tail_chain(
    const float* __restrict__ agg,
    const uint4* __restrict__ fXH,   const uint4* __restrict__ fXL,
    const float* __restrict__ m_input,
    const uint32_t* __restrict__ wf,
    const float* b_rb1b1, const float* b_rb1b2, const float* b_fin,
    const float* b_ra1b1, const float* b_ra1b2,
    const float* b_ra2b1, const float* b_ra2b2,
    float* __restrict__ outp, int E)
{
    extern __shared__ char smem[];
    const uint32_t sb = smem_u32(smem);
    const int tid = threadIdx.x, lane = tid & 31, wid = tid >> 5;
    const int warpM = wid >> 2, warpN = wid & 3;
    const int rt0 = blockIdx.x * 4;

    // stage-0 A: load agg fp32 + split directly into Q
    {
#pragma unroll
        for (int i = 0; i < 2; i++) {
            int f2 = tid + i * 256;
            int ln = f2 & 31, gm = (f2 >> 5) & 3, s = f2 >> 7;
            int r0 = (rt0 + gm) * 16 + (ln >> 2);
            int k0 = s * 16 + 2 * (ln & 3);
            const float* bA = agg + (size_t)r0 * DA_ + k0;
            const float* bB = bA + (size_t)8 * DA_;
            float2 v0 = *(const float2*)bA;
            float2 v1 = *(const float2*)bB;
            float2 v2 = *(const float2*)(bA + 8);
            float2 v3 = *(const float2*)(bB + 8);
            uint4 h, l;
            splitpack2(v0.x, v0.y, h.x, l.x);
            splitpack2(v1.x, v1.y, h.y, l.y);
            splitpack2(v2.x, v2.y, h.z, l.z);
            splitpack2(v3.x, v3.y, h.w, l.w);
            *(uint4*)(smem + TSM_Q + (((s * 2 + 0) * 4 + gm) * 32 + ln) * 16) = h;
            *(uint4*)(smem + TSM_Q + (((s * 2 + 1) * 4 + gm) * 32 + ln) * 16) = l;
        }
    }

    float acc[2][4][4];

    auto prefB = [&](const uint32_t* wfb, int s) {
        int slot = (s < 6) ? s : s - 6;
#pragma unroll
        for (int i = 0; i < 2; i++) {
            int f = tid + i * 256;
            cp_async16(sb + TSM_BS + slot * 8192 + f * 16,
                       (const uint4*)wfb + s * 512 + f);
        }
    };
    auto compute = [&](int aOff, int s) {
        int slot = (s < 6) ? s : s - 6;
        const char* ab = smem + aOff;
        uint4 ahi[2], alo[2];
#pragma unroll
        for (int mt = 0; mt < 2; mt++) {
            int gm = warpM * 2 + mt;
            ahi[mt] = *(const uint4*)(ab + (((s * 2 + 0) * 4 + gm) * 32 + lane) * 16);
            alo[mt] = *(const uint4*)(ab + (((s * 2 + 1) * 4 + gm) * 32 + lane) * 16);
        }
#pragma unroll
        for (int nt = 0; nt < 4; nt++) {
            int gt = warpN * 4 + nt;
            uint4 bq = *(const uint4*)(smem + TSM_BS + slot * 8192 + (gt * 32 + lane) * 16);
            uint32_t bh[2] = {bq.x, bq.y};
            uint32_t bl[2] = {bq.z, bq.w};
#pragma unroll
            for (int mt = 0; mt < 2; mt++) {
                mma_bf16(acc[mt][nt], (const uint32_t*)&ahi[mt], bh);
                mma_bf16(acc[mt][nt], (const uint32_t*)&ahi[mt], bl);
                mma_bf16(acc[mt][nt], (const uint32_t*)&alo[mt], bh);
            }
        }
    };
    // 2 k-steps per sync; 6-slab ring; entry sync frees ring + orders epi writes
    auto runstage = [&](int aOff, const uint32_t* wfb, int KT) {
#pragma unroll
        for (int mt = 0; mt < 2; mt++)
#pragma unroll
            for (int nt = 0; nt < 4; nt++)
#pragma unroll
                for (int j = 0; j < 4; j++) acc[mt][nt][j] = 0.f;
        __syncthreads();
        for (int s = 0; s < 4 && s < KT; s++) { prefB(wfb, s); CP_COMMIT(); }
        const int NP = KT >> 1;
        for (int p = 0; p < NP; p++) {
            if (p + 1 < NP) CP_WAIT(2); else CP_WAIT(0);
            __syncthreads();
            compute(aOff, 2 * p);
            compute(aOff, 2 * p + 1);
            if (2 * p + 4 < KT) { prefB(wfb, 2 * p + 4); CP_COMMIT(); }
            if (2 * p + 5 < KT) { prefB(wfb, 2 * p + 5); CP_COMMIT(); }
        }
    };

    runstage(TSM_Q, wf + OFF_Wup, 4);
    epi_stage64<RES_GFR, false>(smem, acc, nullptr, 0, fXH, fXL, nullptr,
                                TSM_P, nullptr, lane, warpM, warpN, rt0, E);
    runstage(TSM_P, wf + OFF_rb1W1, 8);
    epi_stage64<RES_NONE, false>(smem, acc, b_rb1b1, 0, nullptr, nullptr, nullptr,
                                 TSM_Q, nullptr, lane, warpM, warpN, rt0, E);
    runstage(TSM_Q, wf + OFF_rb1W2, 8);
    epi_stage64<RES_SMEM, false>(smem, acc, b_rb1b2, TSM_P, nullptr, nullptr, nullptr,
                                 TSM_P, nullptr, lane, warpM, warpN, rt0, E);
    runstage(TSM_P, wf + OFF_Wfin, 8);
    epi_stage64<RES_F32, false>(smem, acc, b_fin, 0, nullptr, nullptr, m_input,
                                TSM_Q, nullptr, lane, warpM, warpN, rt0, E);
    runstage(TSM_Q, wf + OFF_ra1W1, 8);
    epi_stage64<RES_NONE, false>(smem, acc, b_ra1b1, 0, nullptr, nullptr, nullptr,
                                 TSM_P, nullptr, lane, warpM, warpN, rt0, E);
    runstage(TSM_P, wf + OFF_ra1W2, 8);
    epi_stage64<RES_SMEM, false>(smem, acc, b_ra1b2, TSM_Q, nullptr, nullptr, nullptr,
                                 TSM_Q, nullptr, lane, warpM, warpN, rt0, E);
    runstage(TSM_Q, wf + OFF_ra2W1, 8);
    epi_stage64<RES_NONE, false>(smem, acc, b_ra2b1, 0, nullptr, nullptr, nullptr,
                                 TSM_P, nullptr, lane, warpM, warpN, rt0, E);
    runstage(TSM_P, wf + OFF_ra2W2, 8);
    epi_stage64<RES_SMEM, true>(smem, acc, b_ra2b2, TSM_Q, nullptr, nullptr, nullptr,
                                0, outp, lane, warpM, warpN, rt0, E);
}

// ---------------- merged weight fragment prep (+wcomb) -------------------------
__global__ void __launch_bounds__(256) k_wfrag_all(
    const float* w0, const float* w1, const float* w2, const float* w3,
    const float* w4, const float* w5, const float* w6, const float* w7,
    const float* w8, const float* w9, const float* w10,
    const float* wrbf1, const float* wrbf2, float* wcomb,
    uint32_t* __restrict__ outv)
{
    int b = blockIdx.x;
    if (b >= 160) {
        int idx = (b - 160) * 256 + threadIdx.x;
        if (idx >= NR_ * D_) return;
        int j = idx / D_, n = idx % D_;
        float s = 0.f;
#pragma unroll
        for (int k = 0; k < DB_; k++) s += wrbf1[j * DB_ + k] * wrbf2[k * D_ + n];
        wcomb[idx] = s;
        return;
    }
    const float* Ws[11] = {w0, w1, w2, w3, w4, w5, w6, w7, w8, w9, w10};
    const float* W;
    int K, N, off, lidx;
    if (b < 144) {
        int w = b / 16;
        W = Ws[w]; K = 128; N = 128;
        off = w * 16384;
        lidx = (b % 16) * 256 + threadIdx.x;
    } else if (b < 152) {
        W = Ws[9]; K = 128; N = 64; off = OFF_Wdown;
        lidx = (b - 144) * 256 + threadIdx.x;
    } else {
        W = Ws[10]; K = 64; N = 128; off = OFF_Wup;
        lidx = (b - 152) * 256 + threadIdx.x;
    }
    int total = (K / 16) * (N / 8) * 32;
    if (lidx >= total) return;
    int lane = lidx & 31;
    int st   = lidx >> 5;
    int t    = st % (N / 8);
    int s    = st / (N / 8);
    int q = lane & 3, r = lane >> 2;
    int n  = t * 8 + r;
    int k0 = s * 16 + 2 * q;
    float a00 = __ldg(W + (size_t)k0 * N + n);
    float a01 = __ldg(W + (size_t)(k0 + 1) * N + n);
    float a10 = __ldg(W + (size_t)(k0 + 8) * N + n);
    float a11 = __ldg(W + (size_t)(k0 + 9) * N + n);
    uint32_t h0, l0, h1, l1;
    splitpack2(a00, a01, h0, l0);
    splitpack2(a10, a11, h1, l1);
    ((uint4*)(outv + off))[lidx] = make_uint4(h0, h1, l0, l1);
}

// ---------------- small kernels -------------------------------------------------
__global__ void __launch_bounds__(256) k_zero(float4* __restrict__ p, int n4) {
    int i = blockIdx.x * blockDim.x + threadIdx.x;
    if (i < n4) p[i] = make_float4(0.f, 0.f, 0.f, 0.f);
}

__global__ void __launch_bounds__(256) k_hsbf(
    const float* __restrict__ sbf, const float* __restrict__ w1,
    float* __restrict__ out, int T)
{
    __shared__ float st[256 * NS_];
    __shared__ float sw[NS_ * DB_];
    for (int i = threadIdx.x; i < NS_ * DB_; i += 256) sw[i] = w1[i];

    int base = blockIdx.x * 256;
    int n = T - base; if (n > 256) n = 256;
    int total = n * NS_;
    int t4 = total >> 2;
    const float4* s4 = (const float4*)(sbf + (size_t)base * NS_);
    for (int i = threadIdx.x; i < t4; i += 256)
        ((float4*)st)[i] = __ldg(s4 + i);
    for (int i = t4 * 4 + threadIdx.x; i < total; i += 256)
        st[i] = sbf[(size_t)base * NS_ + i];
    __syncthreads();

    int r = threadIdx.x;
    if (r >= n) return;
    const float* x = &st[r * NS_];
    float h[DB_];
#pragma unroll
    for (int k = 0; k < DB_; k++) h[k] = 0.f;
#pragma unroll
    for (int j = 0; j < NS_; j++) {
        float xv = x[j];
#pragma unroll
        for (int k = 0; k < DB_; k++) h[k] += xv * sw[j * DB_ + k];
    }
    float4* op = (float4*)(out + (size_t)(base + r) * DB_);
    op[0] = make_float4(h[0], h[1], h[2], h[3]);
    op[1] = make_float4(h[4], h[5], h[6], h[7]);
}

__global__ void __launch_bounds__(256) k_triplet(
    const float* __restrict__ hsbf, const float* __restrict__ wsbf2,
    const int* __restrict__ exp_kj, const int* __restrict__ red_ji,
    const float* __restrict__ down, float* __restrict__ agg, int T)
{
    __shared__ float sw[DB_ * DA_];
    for (int i = threadIdx.x; i < DB_ * DA_; i += 256) sw[i] = wsbf2[i];
    __syncthreads();

    const int q = threadIdx.x & 15;
    float w[DB_][4];
#pragma unroll
    for (int i = 0; i < DB_; i++)
#pragma unroll
        for (int j = 0; j < 4; j++) w[i][j] = sw[i * DA_ + q * 4 + j];

    int t = (blockIdx.x * blockDim.x + threadIdx.x) >> 4;
    const int stride = (gridDim.x * blockDim.x) >> 4;

    for (; t < T; t += stride) {
        int e = __ldg(exp_kj + t);
        int g = __ldg(red_ji + t);
        const float4* hp = (const float4*)(hsbf + (size_t)t * DB_);
        float4 h0 = __ldg(hp), h1 = __ldg(hp + 1);
        float hh[8] = {h0.x, h0.y, h0.z, h0.w, h1.x, h1.y, h1.z, h1.w};

        float s0 = 0.f, s1 = 0.f, s2 = 0.f, s3 = 0.f;
#pragma unroll
        for (int i = 0; i < DB_; i++) {
            s0 += hh[i] * w[i][0];
            s1 += hh[i] * w[i][1];
            s2 += hh[i] * w[i][2];
            s3 += hh[i] * w[i][3];
        }
        float4 a = __ldg((const float4*)(down + (size_t)e * DA_ + q * 4));
        float vx = a.x * s0, vy = a.y * s1, vz = a.z * s2, vw = a.w * s3;

        float* dst = agg + (size_t)g * DA_ + q * 4;
        asm volatile("red.global.add.v4.f32 [%0], {%1, %2, %3, %4};"
                     :: "l"(dst), "f"(vx), "f"(vy), "f"(vz), "f"(vw)
                     : "memory");
    }
}

// ---------------- launch -------------------------------------------------------
extern "C" void kernel_launch(void* const* d_in, const int* in_sizes, int n_in,
                              void* d_out, int out_size)
{
    const float* m_input  = (const float*)d_in[0];
    const float* rbf      = (const float*)d_in[1];
    const float* sbf      = (const float*)d_in[2];
    const float* Wkj      = (const float*)d_in[3];
    const float* bkj      = (const float*)d_in[4];
    const float* Wrbf1    = (const float*)d_in[5];
    const float* Wrbf2    = (const float*)d_in[6];
    const float* Wdown    = (const float*)d_in[7];
    const float* Wsbf1    = (const float*)d_in[8];
    const float* Wsbf2    = (const float*)d_in[9];
    const float* Wup      = (const float*)d_in[10];
    const float* Wji      = (const float*)d_in[11];
    const float* bji      = (const float*)d_in[12];
    const float* rb1_W1   = (const float*)d_in[13];
    const float* rb1_b1   = (const float*)d_in[14];
    const float* rb1_W2   = (const float*)d_in[15];
    const float* rb1_b2   = (const float*)d_in[16];
    const float* Wfin     = (const float*)d_in[17];
    const float* bfin     = (const float*)d_in[18];
    const float* ra1_W1   = (const float*)d_in[19];
    const float* ra1_b1   = (const float*)d_in[20];
    const float* ra1_W2   = (const float*)d_in[21];
    const float* ra1_b2   = (const float*)d_in[22];
    const float* ra2_W1   = (const float*)d_in[23];
    const float* ra2_b1   = (const float*)d_in[24];
    const float* ra2_W2   = (const float*)d_in[25];
    const float* ra2_b2   = (const float*)d_in[26];
    const int*   red_ji   = (const int*)  d_in[27];
    const int*   exp_kj   = (const int*)  d_in[28];

    const int E = in_sizes[0] / D_;
    const int T = in_sizes[27];

    uint4 *fX;
    float *down, *agg, *wcomb, *hsbf;
    uint32_t *wf;
    cudaGetSymbolAddress((void**)&fX,   g_fX);
    cudaGetSymbolAddress((void**)&down, g_down);
    cudaGetSymbolAddress((void**)&agg,  g_agg);
    cudaGetSymbolAddress((void**)&wcomb, g_wcomb);
    cudaGetSymbolAddress((void**)&hsbf, g_hsbf);
    cudaGetSymbolAddress((void**)&wf,   g_wfrag);

    const size_t P8 = (size_t)RT_MAX * 8 * 32;

    float* outp = (float*)d_out;
    const int grid64 = (E + 63) / 64;

    cudaFuncSetAttribute((const void*)head_chain, cudaFuncAttributeMaxDynamicSharedMemorySize, HSM_TOTAL);
    cudaFuncSetAttribute((const void*)tail_chain, cudaFuncAttributeMaxDynamicSharedMemorySize, TSM_TOTAL);

    cudaStream_t s2;
    cudaStreamCreateWithFlags(&s2, cudaStreamNonBlocking);
    cudaEvent_t evFork, evJoin;
    cudaEventCreateWithFlags(&evFork, cudaEventDisableTiming);
    cudaEventCreateWithFlags(&evJoin, cudaEventDisableTiming);

    // fork: s2 runs {zero(agg), hsbf} under the head chain
    cudaEventRecord(evFork, 0);
    cudaStreamWaitEvent(s2, evFork, 0);
    {
        int n4 = (E * DA_) / 4;
        k_zero<<<(n4 + 255) / 256, 256, 0, s2>>>((float4*)agg, n4);
    }
    k_hsbf<<<(T + 255) / 256, 256, 0, s2>>>(sbf, Wsbf1, hsbf, T);
    cudaEventRecord(evJoin, s2);

    // main: weight prep, then fused head (Wkj -> Wdown -> Wji)
    k_wfrag_all<<<163, 256>>>(Wkj, Wji, rb1_W1, rb1_W2, Wfin,
                              ra1_W1, ra1_W2, ra2_W1, ra2_W2, Wdown, Wup,
                              Wrbf1, Wrbf2, wcomb, wf);
    head_chain<<<grid64, 256, HSM_TOTAL>>>(
        m_input, rbf, wf, bkj, bji, wcomb,
        down, fX, fX + P8, E);

    // join: triplet needs hsbf + zeroed agg
    cudaStreamWaitEvent(0, evJoin, 0);

    // triplet -> agg
    k_triplet<<<2048, 256>>>(hsbf, Wsbf2, exp_kj, red_ji, down, agg, T);

    // fused tail (agg split in prologue, 2-step sync cadence):
    // Wup(+fJi) -> rb1 -> Wfin(+m_input) -> ra1 -> ra2 -> out
    tail_chain<<<grid64, 256, TSM_TOTAL>>>(
        agg, fX, fX + P8, m_input, wf,
        rb1_b1, rb1_b2, bfin, ra1_b1, ra1_b2, ra2_b1, ra2_b2,
        outp, E);

    cudaEventDestroy(evFork);
    cudaEventDestroy(evJoin);
    cudaStreamDestroy(s2);
}

// round 16
// speedup vs baseline: 1.0554x; 1.0554x over previous
#include <cuda_runtime.h>
#include <cuda_bf16.h>
#include <cstdint>

// ---------------- problem constants (fixed for this dataset) ----------------
#define D_    128
#define DA_   64
#define DB_   8
#define NR_   6
#define NS_   42
#define E_MAX 200000
#define T_MAX 1600000
#define RT_MAX 12504            // row-tiles of 16

// ---------------- scratch (static device globals; no allocation) ------------
__device__ __align__(16) uint4 g_fX  [(size_t)2 * RT_MAX * 8 * 32];
__device__ __align__(16) float g_down[(size_t)E_MAX * DA_];
__device__ __align__(16) float g_agg [(size_t)E_MAX * DA_];
__device__ __align__(16) float g_wcomb[NR_ * D_];
__device__ __align__(16) float g_hsbf[(size_t)T_MAX * DB_];
__device__ __align__(16) uint32_t g_wfrag[163840];

#define OFF_Wkj    0
#define OFF_Wji    16384
#define OFF_rb1W1  32768
#define OFF_rb1W2  49152
#define OFF_Wfin   65536
#define OFF_ra1W1  81920
#define OFF_ra1W2  98304
#define OFF_ra2W1  114688
#define OFF_ra2W2  131072
#define OFF_Wdown  147456
#define OFF_Wup    155648

// ---------------- helpers ----------------------------------------------------
__device__ __forceinline__ float silu_f(float x) {
    return x / (1.0f + __expf(-x));
}
__device__ __forceinline__ void splitpack2(float x0, float x1,
                                           uint32_t& hi, uint32_t& lo) {
    asm("cvt.rn.bf16x2.f32 %0, %1, %2;" : "=r"(hi) : "f"(x1), "f"(x0));
    float f0 = __uint_as_float(hi << 16);
    float f1 = __uint_as_float(hi & 0xFFFF0000u);
    float l0 = x0 - f0;
    float l1 = x1 - f1;
    asm("cvt.rn.bf16x2.f32 %0, %1, %2;" : "=r"(lo) : "f"(l1), "f"(l0));
}
__device__ __forceinline__ float lo16f(uint32_t u) { return __uint_as_float(u << 16); }
__device__ __forceinline__ float hi16f(uint32_t u) { return __uint_as_float(u & 0xFFFF0000u); }

__device__ __forceinline__ void mma_bf16(float* c, const uint32_t* a, const uint32_t* b) {
    asm volatile(
        "mma.sync.aligned.m16n8k16.row.col.f32.bf16.bf16.f32 "
        "{%0,%1,%2,%3}, {%4,%5,%6,%7}, {%8,%9}, {%0,%1,%2,%3};"
        : "+f"(c[0]), "+f"(c[1]), "+f"(c[2]), "+f"(c[3])
        : "r"(a[0]), "r"(a[1]), "r"(a[2]), "r"(a[3]), "r"(b[0]), "r"(b[1]));
}
__device__ __forceinline__ void cp_async16(uint32_t saddr, const void* gaddr) {
    asm volatile("cp.async.cg.shared.global [%0], [%1], 16;"
                 :: "r"(saddr), "l"(gaddr));
}
#define CP_COMMIT() asm volatile("cp.async.commit_group;" ::: "memory")
#define CP_WAIT(n)  asm volatile("cp.async.wait_group %0;" :: "n"(n) : "memory")
__device__ __forceinline__ uint32_t smem_u32(const void* p) {
    uint32_t a;
    asm("{ .reg .u64 t; cvta.to.shared.u64 t, %1; cvt.u32.u64 %0, t; }" : "=r"(a) : "l"(p));
    return a;
}

// ---------------- fused HEAD chain: Wkj -> Wdown -> Wji, 64 rows/CTA -----------
// (byte-identical to validated R14 version)
#define HSM_BIAS 0                      // bkj[128], bji[128]
#define HSM_WC   1024                   // wcomb 6x128
#define HSM_M    4096                   // 32768: m_input frags
#define HSM_P    (HSM_M + 32768)        // 32768: Wkj output frags
#define HSM_BS   (HSM_P + 32768)        // 4 x 8192 B ring
#define HSM_TOTAL (HSM_BS + 32768)      // 102400

__global__ void __launch_bounds__(256, 2) head_chain(
    const float* __restrict__ m_input, const float* __restrict__ rbf,
    const uint32_t* __restrict__ wf,
    const float* __restrict__ bkj, const float* __restrict__ bji,
    const float* __restrict__ wcombG,
    float* __restrict__ down,
    uint4* __restrict__ fXH, uint4* __restrict__ fXL, int E)
{
    extern __shared__ char smem[];
    const uint32_t sb = smem_u32(smem);
    const int tid = threadIdx.x, lane = tid & 31, wid = tid >> 5;
    const int warpM = wid >> 2, warpN = wid & 3;
    const int rt0 = blockIdx.x * 4;                 // 64 rows per CTA

    if (tid < 128) {
        ((float*)(smem + HSM_BIAS))[tid]       = bkj[tid];
        ((float*)(smem + HSM_BIAS))[128 + tid] = bji[tid];
    }
    for (int i = tid; i < NR_ * D_; i += 256)
        ((float*)(smem + HSM_WC))[i] = wcombG[i];

    // ---- A preload + split (once) into M ----
#pragma unroll
    for (int i = 0; i < 4; i++) {
        int f = tid + i * 256;
        int ln = f & 31, gm = (f >> 5) & 3, s = f >> 7;
        int r0 = rt0 * 16 + gm * 16 + (ln >> 2);
        int k0 = s * 16 + 2 * (ln & 3);
        int rA = (r0     < E) ? r0     : E - 1;
        int rB = (r0 + 8 < E) ? r0 + 8 : E - 1;
        const float* bA = m_input + (size_t)rA * D_ + k0;
        const float* bB = m_input + (size_t)rB * D_ + k0;
        float2 v0 = *(const float2*)bA;
        float2 v1 = *(const float2*)bB;
        float2 v2 = *(const float2*)(bA + 8);
        float2 v3 = *(const float2*)(bB + 8);
        uint4 h, l;
        splitpack2(v0.x, v0.y, h.x, l.x);
        splitpack2(v1.x, v1.y, h.y, l.y);
        splitpack2(v2.x, v2.y, h.z, l.z);
        splitpack2(v3.x, v3.y, h.w, l.w);
        *(uint4*)(smem + HSM_M + (((s * 2 + 0) * 4 + gm) * 32 + ln) * 16) = h;
        *(uint4*)(smem + HSM_M + (((s * 2 + 1) * 4 + gm) * 32 + ln) * 16) = l;
    }

    float acc[2][4][4];

    auto prefB = [&](const uint32_t* wfb, int s, int nq4) {
#pragma unroll
        for (int i = 0; i < 2; i++) {
            int f = tid + i * 256;
            if (f < nq4)
                cp_async16(sb + HSM_BS + (s & 3) * 8192 + f * 16,
                           (const uint4*)wfb + s * nq4 + f);
        }
    };
    auto compute128 = [&](int aOff, int s) {
        const char* ab = smem + aOff;
        uint4 ahi[2], alo[2];
#pragma unroll
        for (int mt = 0; mt < 2; mt++) {
            int gm = warpM * 2 + mt;
            ahi[mt] = *(const uint4*)(ab + (((s * 2 + 0) * 4 + gm) * 32 + lane) * 16);
            alo[mt] = *(const uint4*)(ab + (((s * 2 + 1) * 4 + gm) * 32 + lane) * 16);
        }
#pragma unroll
        for (int nt = 0; nt < 4; nt++) {
            int gt = warpN * 4 + nt;
            uint4 bq = *(const uint4*)(smem + HSM_BS + (s & 3) * 8192 + (gt * 32 + lane) * 16);
            uint32_t bh[2] = {bq.x, bq.y};
            uint32_t bl[2] = {bq.z, bq.w};
#pragma unroll
            for (int mt = 0; mt < 2; mt++) {
                mma_bf16(acc[mt][nt], (const uint32_t*)&ahi[mt], bh);
                mma_bf16(acc[mt][nt], (const uint32_t*)&ahi[mt], bl);
                mma_bf16(acc[mt][nt], (const uint32_t*)&alo[mt], bh);
            }
        }
    };
    auto runstage128 = [&](int aOff, const uint32_t* wfb) {
#pragma unroll
        for (int mt = 0; mt < 2; mt++)
#pragma unroll
            for (int nt = 0; nt < 4; nt++)
#pragma unroll
                for (int j = 0; j < 4; j++) acc[mt][nt][j] = 0.f;
        prefB(wfb, 0, 512); CP_COMMIT();
        prefB(wfb, 1, 512); CP_COMMIT();
        for (int s = 0; s < 8; s++) {
            if (s + 2 < 8) { prefB(wfb, s + 2, 512); CP_COMMIT(); }
            if (s + 2 < 8)      CP_WAIT(2);
            else if (s + 1 < 8) CP_WAIT(1);
            else                CP_WAIT(0);
            __syncthreads();
            compute128(aOff, s);
        }
    };

    // ================= S0: Wkj (A=M) -> P, epi silu(+bkj) * rbfmod ============
    runstage128(HSM_M, wf + OFF_Wkj);
    {
        float* sBk = (float*)(smem + HSM_BIAS);
        float* sWc = (float*)(smem + HSM_WC);
#pragma unroll
        for (int mt = 0; mt < 2; mt++) {
            const int rtg = rt0 + warpM * 2 + mt;
            const int gm  = warpM * 2 + mt;
            float o[4][4];
#pragma unroll
            for (int nt = 0; nt < 4; nt++) {
                int col = warpN * 32 + nt * 8 + 2 * (lane & 3);
#pragma unroll
                for (int half = 0; half < 2; half++) {
                    o[nt][half * 2 + 0] = silu_f(acc[mt][nt][half * 2 + 0] + sBk[col]);
                    o[nt][half * 2 + 1] = silu_f(acc[mt][nt][half * 2 + 1] + sBk[col + 1]);
                }
            }
            int rA = rtg * 16 + (lane >> 2);
            int rB = rA + 8;
            if (rA >= E) rA = E - 1;
            if (rB >= E) rB = E - 1;
            const float* pa = rbf + (size_t)rA * NR_;
            const float* pb = rbf + (size_t)rB * NR_;
            float2 a0 = __ldg((const float2*)pa), a1 = __ldg((const float2*)pa + 1),
                   a2 = __ldg((const float2*)pa + 2);
            float2 b0 = __ldg((const float2*)pb), b1 = __ldg((const float2*)pb + 1),
                   b2 = __ldg((const float2*)pb + 2);
            float hA[6] = {a0.x, a0.y, a1.x, a1.y, a2.x, a2.y};
            float hB[6] = {b0.x, b0.y, b1.x, b1.y, b2.x, b2.y};
#pragma unroll
            for (int nt = 0; nt < 4; nt++) {
                int col = warpN * 32 + nt * 8 + 2 * (lane & 3);
                float r0 = 0.f, r1 = 0.f, r2 = 0.f, r3 = 0.f;
#pragma unroll
                for (int j = 0; j < NR_; j++) {
                    float w0 = sWc[j * D_ + col], w1 = sWc[j * D_ + col + 1];
                    r0 += hA[j] * w0; r1 += hA[j] * w1;
                    r2 += hB[j] * w0; r3 += hB[j] * w1;
                }
                o[nt][0] *= r0; o[nt][1] *= r1; o[nt][2] *= r2; o[nt][3] *= r3;
            }
#pragma unroll
            for (int j = 0; j < 2; j++) {
                uint4 h, l;
                splitpack2(o[2 * j][0],     o[2 * j][1],     h.x, l.x);
                splitpack2(o[2 * j][2],     o[2 * j][3],     h.y, l.y);
                splitpack2(o[2 * j + 1][0], o[2 * j + 1][1], h.z, l.z);
                splitpack2(o[2 * j + 1][2], o[2 * j + 1][3], h.w, l.w);
                int sp = warpN * 2 + j;
                *(uint4*)(smem + HSM_P + (((sp * 2 + 0) * 4 + gm) * 32 + lane) * 16) = h;
                *(uint4*)(smem + HSM_P + (((sp * 2 + 1) * 4 + gm) * 32 + lane) * 16) = l;
            }
        }
    }

    // ================= S1: Wdown (A=P, NT=64) -> down fp32 global =============
    {
        const int gm4 = wid >> 1;       // 0..3 (16 rows each)
        const int wn2 = wid & 1;        // 0..1 (32 cols each)
        float a1acc[4][4];
#pragma unroll
        for (int nt = 0; nt < 4; nt++)
#pragma unroll
            for (int j = 0; j < 4; j++) a1acc[nt][j] = 0.f;
        const uint32_t* wfb = wf + OFF_Wdown;
        prefB(wfb, 0, 256); CP_COMMIT();
        prefB(wfb, 1, 256); CP_COMMIT();
        for (int s = 0; s < 8; s++) {
            if (s + 2 < 8) { prefB(wfb, s + 2, 256); CP_COMMIT(); }
            if (s + 2 < 8)      CP_WAIT(2);
            else if (s + 1 < 8) CP_WAIT(1);
            else                CP_WAIT(0);
            __syncthreads();
            const char* ab = smem + HSM_P;
            uint4 ahi = *(const uint4*)(ab + (((s * 2 + 0) * 4 + gm4) * 32 + lane) * 16);
            uint4 alo = *(const uint4*)(ab + (((s * 2 + 1) * 4 + gm4) * 32 + lane) * 16);
#pragma unroll
            for (int nt = 0; nt < 4; nt++) {
                int gt = wn2 * 4 + nt;
                uint4 bq = *(const uint4*)(smem + HSM_BS + (s & 3) * 8192 + (gt * 32 + lane) * 16);
                uint32_t bh[2] = {bq.x, bq.y};
                uint32_t bl[2] = {bq.z, bq.w};
                mma_bf16(a1acc[nt], (const uint32_t*)&ahi, bh);
                mma_bf16(a1acc[nt], (const uint32_t*)&ahi, bl);
                mma_bf16(a1acc[nt], (const uint32_t*)&alo, bh);
            }
        }
        const int rtg = rt0 + gm4;
#pragma unroll
        for (int nt = 0; nt < 4; nt++) {
            int col = wn2 * 32 + nt * 8 + 2 * (lane & 3);
#pragma unroll
            for (int half = 0; half < 2; half++) {
                int row = rtg * 16 + (lane >> 2) + half * 8;
                if (row < E)
                    *(float2*)(down + (size_t)row * DA_ + col) =
                        make_float2(silu_f(a1acc[nt][half * 2 + 0]),
                                    silu_f(a1acc[nt][half * 2 + 1]));
            }
        }
    }

    // ================= S2: Wji (A=M) -> fX frag global, epi silu(+bji) ========
    runstage128(HSM_M, wf + OFF_Wji);
    {
        float* sBj = (float*)(smem + HSM_BIAS) + 128;
#pragma unroll
        for (int mt = 0; mt < 2; mt++) {
            const int rtg = rt0 + warpM * 2 + mt;
            float o[4][4];
#pragma unroll
            for (int nt = 0; nt < 4; nt++) {
                int col = warpN * 32 + nt * 8 + 2 * (lane & 3);
#pragma unroll
                for (int half = 0; half < 2; half++) {
                    o[nt][half * 2 + 0] = silu_f(acc[mt][nt][half * 2 + 0] + sBj[col]);
                    o[nt][half * 2 + 1] = silu_f(acc[mt][nt][half * 2 + 1] + sBj[col + 1]);
                }
            }
#pragma unroll
            for (int j = 0; j < 2; j++) {
                uint4 h, l;
                splitpack2(o[2 * j][0],     o[2 * j][1],     h.x, l.x);
                splitpack2(o[2 * j][2],     o[2 * j][3],     h.y, l.y);
                splitpack2(o[2 * j + 1][0], o[2 * j + 1][1], h.z, l.z);
                splitpack2(o[2 * j + 1][2], o[2 * j + 1][3], h.w, l.w);
                int q = (rtg * 8 + warpN * 2 + j) * 32 + lane;
                fXH[q] = h;
                fXL[q] = l;
            }
        }
    }
}

// ---------------- fused 8-GEMM TAIL chain (validated R14: 4-slab, 1 step/sync) -
#define RES_NONE 0
#define RES_SMEM 1
#define RES_GFR  2
#define RES_F32  3

#define TSM_BIAS 0
#define TSM_P    4096
#define TSM_Q    (TSM_P + 32768)
#define TSM_BS   (TSM_Q + 32768)
#define TSM_TOTAL (TSM_BS + 32768)     // 102400

template<int RES, bool OUTG>
__device__ __forceinline__ void epi_stage64(
    char* smem, float (&acc)[2][4][4], const float* sBiasG,
    int resOff, const uint4* gResH, const uint4* gResL, const float* resF,
    int outOff, float* outF,
    int lane, int warpM, int warpN, int rt0, int E)
{
#pragma unroll
    for (int mt = 0; mt < 2; mt++) {
        const int rtg = rt0 + warpM * 2 + mt;
        const int gm  = warpM * 2 + mt;
        float o[4][4];
#pragma unroll
        for (int nt = 0; nt < 4; nt++) {
            int col = warpN * 32 + nt * 8 + 2 * (lane & 3);
            float b0 = sBiasG ? sBiasG[col]     : 0.f;
            float b1 = sBiasG ? sBiasG[col + 1] : 0.f;
#pragma unroll
            for (int half = 0; half < 2; half++) {
                o[nt][half * 2 + 0] = silu_f(acc[mt][nt][half * 2 + 0] + b0);
                o[nt][half * 2 + 1] = silu_f(acc[mt][nt][half * 2 + 1] + b1);
            }
        }
        if (RES == RES_SMEM || RES == RES_GFR) {
#pragma unroll
            for (int j = 0; j < 2; j++) {
                uint4 rh, rl;
                int sp = warpN * 2 + j;
                if (RES == RES_SMEM) {
                    rh = *(const uint4*)(smem + resOff + (((sp * 2 + 0) * 4 + gm) * 32 + lane) * 16);
                    rl = *(const uint4*)(smem + resOff + (((sp * 2 + 1) * 4 + gm) * 32 + lane) * 16);
                } else {
                    int q = (rtg * 8 + sp) * 32 + lane;
                    rh = __ldg(gResH + q);
                    rl = __ldg(gResL + q);
                }
                o[2 * j    ][0] += lo16f(rh.x) + lo16f(rl.x);
                o[2 * j    ][1] += hi16f(rh.x) + hi16f(rl.x);
                o[2 * j    ][2] += lo16f(rh.y) + lo16f(rl.y);
                o[2 * j    ][3] += hi16f(rh.y) + hi16f(rl.y);
                o[2 * j + 1][0] += lo16f(rh.z) + lo16f(rl.z);
                o[2 * j + 1][1] += hi16f(rh.z) + hi16f(rl.z);
                o[2 * j + 1][2] += lo16f(rh.w) + lo16f(rl.w);
                o[2 * j + 1][3] += hi16f(rh.w) + hi16f(rl.w);
            }
        } else if (RES == RES_F32) {
#pragma unroll
            for (int nt = 0; nt < 4; nt++) {
                int col = warpN * 32 + nt * 8 + 2 * (lane & 3);
#pragma unroll
                for (int half = 0; half < 2; half++) {
                    int row = rtg * 16 + (lane >> 2) + half * 8;
                    if (row >= E) row = E - 1;
                    float2 rr = __ldg((const float2*)(resF + (size_t)row * D_ + col));
                    o[nt][half * 2 + 0] += rr.x;
                    o[nt][half * 2 + 1] += rr.y;
                }
            }
        }
        if (OUTG) {
#pragma unroll
            for (int nt = 0; nt < 4; nt++) {
                int col = warpN * 32 + nt * 8 + 2 * (lane & 3);
#pragma unroll
                for (int half = 0; half < 2; half++) {
                    int row = rtg * 16 + (lane >> 2) + half * 8;
                    if (row < E)
                        *(float2*)(outF + (size_t)row * D_ + col) =
                            make_float2(o[nt][half * 2], o[nt][half * 2 + 1]);
                }
            }
        } else {
#pragma unroll
            for (int j = 0; j < 2; j++) {
                uint4 h, l;
                splitpack2(o[2 * j][0],     o[2 * j][1],     h.x, l.x);
                splitpack2(o[2 * j][2],     o[2 * j][3],     h.y, l.y);
                splitpack2(o[2 * j + 1][0], o[2 * j + 1][1], h.z, l.z);
                splitpack2(o[2 * j + 1][2], o[2 * j + 1][3], h.w, l.w);
                int sp = warpN * 2 + j;
                *(uint4*)(smem + outOff + (((sp * 2 + 0) * 4 + gm) * 32 + lane) * 16) = h;
                *(uint4*)(smem + outOff + (((sp * 2 + 1) * 4 + gm) * 32 + lane) * 16) = l;
            }
        }
    }
}

__global__ void __launch_bounds__(256, 2) tail_chain(
    const float* __restrict__ agg,
    const uint4* __restrict__ fXH,   const uint4* __restrict__ fXL,
    const float* __restrict__ m_input,
    const uint32_t* __restrict__ wf,
    const float* b_rb1b1, const float* b_rb1b2, const float* b_fin,
    const float* b_ra1b1, const float* b_ra1b2,
    const float* b_ra2b1, const float* b_ra2b2,
    float* __restrict__ outp, int E)
{
    extern __shared__ char smem[];
    const uint32_t sb = smem_u32(smem);
    const int tid = threadIdx.x, lane = tid & 31, wid = tid >> 5;
    const int warpM = wid >> 2, warpN = wid & 3;
    const int rt0 = blockIdx.x * 4;

    {
        const float* bs[7] = {b_rb1b1, b_rb1b2, b_fin, b_ra1b1, b_ra1b2, b_ra2b1, b_ra2b2};
        if (tid < 128)
#pragma unroll
            for (int g = 0; g < 7; g++)
                ((float*)(smem + TSM_BIAS))[g * 128 + tid] = bs[g][tid];
    }
    float* sB = (float*)(smem + TSM_BIAS);

    // stage-0 A: load agg fp32 + split directly into Q (replaces k_asplit)
    {
#pragma unroll
        for (int i = 0; i < 2; i++) {
            int f2 = tid + i * 256;
            int ln = f2 & 31, gm = (f2 >> 5) & 3, s = f2 >> 7;
            int r0 = (rt0 + gm) * 16 + (ln >> 2);
            int k0 = s * 16 + 2 * (ln & 3);
            const float* bA = agg + (size_t)r0 * DA_ + k0;
            const float* bB = bA + (size_t)8 * DA_;
            float2 v0 = *(const float2*)bA;
            float2 v1 = *(const float2*)bB;
            float2 v2 = *(const float2*)(bA + 8);
            float2 v3 = *(const float2*)(bB + 8);
            uint4 h, l;
            splitpack2(v0.x, v0.y, h.x, l.x);
            splitpack2(v1.x, v1.y, h.y, l.y);
            splitpack2(v2.x, v2.y, h.z, l.z);
            splitpack2(v3.x, v3.y, h.w, l.w);
            *(uint4*)(smem + TSM_Q + (((s * 2 + 0) * 4 + gm) * 32 + ln) * 16) = h;
            *(uint4*)(smem + TSM_Q + (((s * 2 + 1) * 4 + gm) * 32 + ln) * 16) = l;
        }
    }

    float acc[2][4][4];

    auto prefB = [&](const uint32_t* wfb, int s) {
#pragma unroll
        for (int i = 0; i < 2; i++) {
            int f = tid + i * 256;
            cp_async16(sb + TSM_BS + (s & 3) * 8192 + f * 16,
                       (const uint4*)wfb + s * 512 + f);
        }
    };
    auto compute = [&](int aOff, int s) {
        const char* ab = smem + aOff;
        uint4 ahi[2], alo[2];
#pragma unroll
        for (int mt = 0; mt < 2; mt++) {
            int gm = warpM * 2 + mt;
            ahi[mt] = *(const uint4*)(ab + (((s * 2 + 0) * 4 + gm) * 32 + lane) * 16);
            alo[mt] = *(const uint4*)(ab + (((s * 2 + 1) * 4 + gm) * 32 + lane) * 16);
        }
#pragma unroll
        for (int nt = 0; nt < 4; nt++) {
            int gt = warpN * 4 + nt;
            uint4 bq = *(const uint4*)(smem + TSM_BS + (s & 3) * 8192 + (gt * 32 + lane) * 16);
            uint32_t bh[2] = {bq.x, bq.y};
            uint32_t bl[2] = {bq.z, bq.w};
#pragma unroll
            for (int mt = 0; mt < 2; mt++) {
                mma_bf16(acc[mt][nt], (const uint32_t*)&ahi[mt], bh);
                mma_bf16(acc[mt][nt], (const uint32_t*)&ahi[mt], bl);
                mma_bf16(acc[mt][nt], (const uint32_t*)&alo[mt], bh);
            }
        }
    };
    auto runstage = [&](int aOff, const uint32_t* wfb, int KT) {
#pragma unroll
        for (int mt = 0; mt < 2; mt++)
#pragma unroll
            for (int nt = 0; nt < 4; nt++)
#pragma unroll
                for (int j = 0; j < 4; j++) acc[mt][nt][j] = 0.f;
        prefB(wfb, 0); CP_COMMIT();
        prefB(wfb, 1); CP_COMMIT();
        for (int s = 0; s < KT; s++) {
            if (s + 2 < KT) { prefB(wfb, s + 2); CP_COMMIT(); }
            if (s + 2 < KT)      CP_WAIT(2);
            else if (s + 1 < KT) CP_WAIT(1);
            else                 CP_WAIT(0);
            __syncthreads();
            compute(aOff, s);
        }
    };

    runstage(TSM_Q, wf + OFF_Wup, 4);
    epi_stage64<RES_GFR, false>(smem, acc, nullptr, 0, fXH, fXL, nullptr,
                                TSM_P, nullptr, lane, warpM, warpN, rt0, E);
    runstage(TSM_P, wf + OFF_rb1W1, 8);
    epi_stage64<RES_NONE, false>(smem, acc, sB + 0 * 128, 0, nullptr, nullptr, nullptr,
                                 TSM_Q, nullptr, lane, warpM, warpN, rt0, E);
    runstage(TSM_Q, wf + OFF_rb1W2, 8);
    epi_stage64<RES_SMEM, false>(smem, acc, sB + 1 * 128, TSM_P, nullptr, nullptr, nullptr,
                                 TSM_P, nullptr, lane, warpM, warpN, rt0, E);
    runstage(TSM_P, wf + OFF_Wfin, 8);
    epi_stage64<RES_F32, false>(smem, acc, sB + 2 * 128, 0, nullptr, nullptr, m_input,
                                TSM_Q, nullptr, lane, warpM, warpN, rt0, E);
    runstage(TSM_Q, wf + OFF_ra1W1, 8);
    epi_stage64<RES_NONE, false>(smem, acc, sB + 3 * 128, 0, nullptr, nullptr, nullptr,
                                 TSM_P, nullptr, lane, warpM, warpN, rt0, E);
    runstage(TSM_P, wf + OFF_ra1W2, 8);
    epi_stage64<RES_SMEM, false>(smem, acc, sB + 4 * 128, TSM_Q, nullptr, nullptr, nullptr,
                                 TSM_Q, nullptr, lane, warpM, warpN, rt0, E);
    runstage(TSM_Q, wf + OFF_ra2W1, 8);
    epi_stage64<RES_NONE, false>(smem, acc, sB + 5 * 128, 0, nullptr, nullptr, nullptr,
                                 TSM_P, nullptr, lane, warpM, warpN, rt0, E);
    runstage(TSM_P, wf + OFF_ra2W2, 8);
    epi_stage64<RES_SMEM, true>(smem, acc, sB + 6 * 128, TSM_Q, nullptr, nullptr, nullptr,
                                0, outp, lane, warpM, warpN, rt0, E);
}

// ---------------- weight fragment prep (shared worker) -------------------------
__device__ __forceinline__ void wfrag_one(
    const float* __restrict__ W, int K, int N, int off, int lidx,
    uint32_t* __restrict__ outv)
{
    int total = (K / 16) * (N / 8) * 32;
    if (lidx >= total) return;
    int lane = lidx & 31;
    int st   = lidx >> 5;
    int t    = st % (N / 8);
    int s    = st / (N / 8);
    int q = lane & 3, r = lane >> 2;
    int n  = t * 8 + r;
    int k0 = s * 16 + 2 * q;
    float a00 = __ldg(W + (size_t)k0 * N + n);
    float a01 = __ldg(W + (size_t)(k0 + 1) * N + n);
    float a10 = __ldg(W + (size_t)(k0 + 8) * N + n);
    float a11 = __ldg(W + (size_t)(k0 + 9) * N + n);
    uint32_t h0, l0, h1, l1;
    splitpack2(a00, a01, h0, l0);
    splitpack2(a10, a11, h1, l1);
    ((uint4*)(outv + off))[lidx] = make_uint4(h0, h1, l0, l1);
}

// head group: Wkj(16) + Wji(16) + Wdown(8) + wcomb(3) = 43 blocks
__global__ void __launch_bounds__(256) k_wfrag_head(
    const float* Wkj, const float* Wji, const float* Wdown,
    const float* wrbf1, const float* wrbf2, float* wcomb,
    uint32_t* __restrict__ outv)
{
    int b = blockIdx.x;
    if (b < 16)      wfrag_one(Wkj,   128, 128, OFF_Wkj,   b * 256 + threadIdx.x, outv);
    else if (b < 32) wfrag_one(Wji,   128, 128, OFF_Wji,   (b - 16) * 256 + threadIdx.x, outv);
    else if (b < 40) wfrag_one(Wdown, 128, 64,  OFF_Wdown, (b - 32) * 256 + threadIdx.x, outv);
    else {
        int idx = (b - 40) * 256 + threadIdx.x;
        if (idx >= NR_ * D_) return;
        int j = idx / D_, n = idx % D_;
        float s = 0.f;
#pragma unroll
        for (int k = 0; k < DB_; k++) s += wrbf1[j * DB_ + k] * wrbf2[k * D_ + n];
        wcomb[idx] = s;
    }
}

// tail group: 7 x D^2 weights (112) + Wup(8) = 120 blocks
__global__ void __launch_bounds__(256) k_wfrag_tail(
    const float* w0, const float* w1, const float* w2, const float* w3,
    const float* w4, const float* w5, const float* w6, const float* Wup,
    uint32_t* __restrict__ outv)
{
    const float* Ws[7] = {w0, w1, w2, w3, w4, w5, w6};
    const int offs[7] = {OFF_rb1W1, OFF_rb1W2, OFF_Wfin,
                         OFF_ra1W1, OFF_ra1W2, OFF_ra2W1, OFF_ra2W2};
    int b = blockIdx.x;
    if (b < 112) {
        int w = b / 16;
        wfrag_one(Ws[w], 128, 128, offs[w], (b % 16) * 256 + threadIdx.x, outv);
    } else {
        wfrag_one(Wup, 64, 128, OFF_Wup, (b - 112) * 256 + threadIdx.x, outv);
    }
}

// ---------------- small kernels -------------------------------------------------
__global__ void __launch_bounds__(256) k_zero(float4* __restrict__ p, int n4) {
    int i = blockIdx.x * blockDim.x + threadIdx.x;
    if (i < n4) p[i] = make_float4(0.f, 0.f, 0.f, 0.f);
}

__global__ void __launch_bounds__(256) k_hsbf(
    const float* __restrict__ sbf, const float* __restrict__ w1,
    float* __restrict__ out, int T)
{
    __shared__ float st[256 * NS_];
    __shared__ float sw[NS_ * DB_];
    for (int i = threadIdx.x; i < NS_ * DB_; i += 256) sw[i] = w1[i];

    int base = blockIdx.x * 256;
    int n = T - base; if (n > 256) n = 256;
    int total = n * NS_;
    int t4 = total >> 2;
    const float4* s4 = (const float4*)(sbf + (size_t)base * NS_);
    for (int i = threadIdx.x; i < t4; i += 256)
        ((float4*)st)[i] = __ldg(s4 + i);
    for (int i = t4 * 4 + threadIdx.x; i < total; i += 256)
        st[i] = sbf[(size_t)base * NS_ + i];
    __syncthreads();

    int r = threadIdx.x;
    if (r >= n) return;
    const float* x = &st[r * NS_];
    float h[DB_];
#pragma unroll
    for (int k = 0; k < DB_; k++) h[k] = 0.f;
#pragma unroll
    for (int j = 0; j < NS_; j++) {
        float xv = x[j];
#pragma unroll
        for (int k = 0; k < DB_; k++) h[k] += xv * sw[j * DB_ + k];
    }
    float4* op = (float4*)(out + (size_t)(base + r) * DB_);
    op[0] = make_float4(h[0], h[1], h[2], h[3]);
    op[1] = make_float4(h[4], h[5], h[6], h[7]);
}

__global__ void __launch_bounds__(256) k_triplet(
    const float* __restrict__ hsbf, const float* __restrict__ wsbf2,
    const int* __restrict__ exp_kj, const int* __restrict__ red_ji,
    const float* __restrict__ down, float* __restrict__ agg, int T)
{
    __shared__ float sw[DB_ * DA_];
    for (int i = threadIdx.x; i < DB_ * DA_; i += 256) sw[i] = wsbf2[i];
    __syncthreads();

    const int q = threadIdx.x & 15;
    float w[DB_][4];
#pragma unroll
    for (int i = 0; i < DB_; i++)
#pragma unroll
        for (int j = 0; j < 4; j++) w[i][j] = sw[i * DA_ + q * 4 + j];

    int t = (blockIdx.x * blockDim.x + threadIdx.x) >> 4;
    const int stride = (gridDim.x * blockDim.x) >> 4;

    for (; t < T; t += stride) {
        int e = __ldg(exp_kj + t);
        int g = __ldg(red_ji + t);
        const float4* hp = (const float4*)(hsbf + (size_t)t * DB_);
        float4 h0 = __ldg(hp), h1 = __ldg(hp + 1);
        float hh[8] = {h0.x, h0.y, h0.z, h0.w, h1.x, h1.y, h1.z, h1.w};

        float s0 = 0.f, s1 = 0.f, s2 = 0.f, s3 = 0.f;
#pragma unroll
        for (int i = 0; i < DB_; i++) {
            s0 += hh[i] * w[i][0];
            s1 += hh[i] * w[i][1];
            s2 += hh[i] * w[i][2];
            s3 += hh[i] * w[i][3];
        }
        float4 a = __ldg((const float4*)(down + (size_t)e * DA_ + q * 4));
        float vx = a.x * s0, vy = a.y * s1, vz = a.z * s2, vw = a.w * s3;

        float* dst = agg + (size_t)g * DA_ + q * 4;
        asm volatile("red.global.add.v4.f32 [%0], {%1, %2, %3, %4};"
                     :: "l"(dst), "f"(vx), "f"(vy), "f"(vz), "f"(vw)
                     : "memory");
    }
}

// ---------------- launch -------------------------------------------------------
extern "C" void kernel_launch(void* const* d_in, const int* in_sizes, int n_in,
                              void* d_out, int out_size)
{
    const float* m_input  = (const float*)d_in[0];
    const float* rbf      = (const float*)d_in[1];
    const float* sbf      = (const float*)d_in[2];
    const float* Wkj      = (const float*)d_in[3];
    const float* bkj      = (const float*)d_in[4];
    const float* Wrbf1    = (const float*)d_in[5];
    const float* Wrbf2    = (const float*)d_in[6];
    const float* Wdown    = (const float*)d_in[7];
    const float* Wsbf1    = (const float*)d_in[8];
    const float* Wsbf2    = (const float*)d_in[9];
    const float* Wup      = (const float*)d_in[10];
    const float* Wji      = (const float*)d_in[11];
    const float* bji      = (const float*)d_in[12];
    const float* rb1_W1   = (const float*)d_in[13];
    const float* rb1_b1   = (const float*)d_in[14];
    const float* rb1_W2   = (const float*)d_in[15];
    const float* rb1_b2   = (const float*)d_in[16];
    const float* Wfin     = (const float*)d_in[17];
    const float* bfin     = (const float*)d_in[18];
    const float* ra1_W1   = (const float*)d_in[19];
    const float* ra1_b1   = (const float*)d_in[20];
    const float* ra1_W2   = (const float*)d_in[21];
    const float* ra1_b2   = (const float*)d_in[22];
    const float* ra2_W1   = (const float*)d_in[23];
    const float* ra2_b1   = (const float*)d_in[24];
    const float* ra2_W2   = (const float*)d_in[25];
    const float* ra2_b2   = (const float*)d_in[26];
    const int*   red_ji   = (const int*)  d_in[27];
    const int*   exp_kj   = (const int*)  d_in[28];

    const int E = in_sizes[0] / D_;
    const int T = in_sizes[27];

    uint4 *fX;
    float *down, *agg, *wcomb, *hsbf;
    uint32_t *wf;
    cudaGetSymbolAddress((void**)&fX,   g_fX);
    cudaGetSymbolAddress((void**)&down, g_down);
    cudaGetSymbolAddress((void**)&agg,  g_agg);
    cudaGetSymbolAddress((void**)&wcomb, g_wcomb);
    cudaGetSymbolAddress((void**)&hsbf, g_hsbf);
    cudaGetSymbolAddress((void**)&wf,   g_wfrag);

    const size_t P8 = (size_t)RT_MAX * 8 * 32;

    float* outp = (float*)d_out;
    const int grid64 = (E + 63) / 64;

    cudaFuncSetAttribute((const void*)head_chain, cudaFuncAttributeMaxDynamicSharedMemorySize, HSM_TOTAL);
    cudaFuncSetAttribute((const void*)tail_chain, cudaFuncAttributeMaxDynamicSharedMemorySize, TSM_TOTAL);

    cudaStream_t s2;
    cudaStreamCreateWithFlags(&s2, cudaStreamNonBlocking);
    cudaEvent_t evFork, evJoin;
    cudaEventCreateWithFlags(&evFork, cudaEventDisableTiming);
    cudaEventCreateWithFlags(&evJoin, cudaEventDisableTiming);

    // fork: s2 runs {zero(agg), hsbf, tail-weight prep} under the head chain
    cudaEventRecord(evFork, 0);
    cudaStreamWaitEvent(s2, evFork, 0);
    {
        int n4 = (E * DA_) / 4;
        k_zero<<<(n4 + 255) / 256, 256, 0, s2>>>((float4*)agg, n4);
    }
    k_hsbf<<<(T + 255) / 256, 256, 0, s2>>>(sbf, Wsbf1, hsbf, T);
    k_wfrag_tail<<<120, 256, 0, s2>>>(rb1_W1, rb1_W2, Wfin,
                                      ra1_W1, ra1_W2, ra2_W1, ra2_W2, Wup, wf);
    cudaEventRecord(evJoin, s2);

    // main: head weight prep, then fused head (Wkj -> Wdown -> Wji)
    k_wfrag_head<<<43, 256>>>(Wkj, Wji, Wdown, Wrbf1, Wrbf2, wcomb, wf);
    head_chain<<<grid64, 256, HSM_TOTAL>>>(
        m_input, rbf, wf, bkj, bji, wcomb,
        down, fX, fX + P8, E);

    // join: triplet needs hsbf + zeroed agg (and tail weights before tail_chain)
    cudaStreamWaitEvent(0, evJoin, 0);

    // triplet -> agg
    k_triplet<<<2048, 256>>>(hsbf, Wsbf2, exp_kj, red_ji, down, agg, T);

    // fused tail (agg split in prologue): Wup(+fJi) -> rb1 -> Wfin(+m_input)
    // -> ra1 -> ra2 -> out
    tail_chain<<<grid64, 256, TSM_TOTAL>>>(
        agg, fX, fX + P8, m_input, wf,
        rb1_b1, rb1_b2, bfin, ra1_b1, ra1_b2, ra2_b1, ra2_b2,
        outp, E);

    cudaEventDestroy(evFork);
    cudaEventDestroy(evJoin);
    cudaStreamDestroy(s2);
}

// round 17
// speedup vs baseline: 1.0811x; 1.0244x over previous
#include <cuda_runtime.h>
#include <cuda_bf16.h>
#include <cstdint>

// ---------------- problem constants (fixed for this dataset) ----------------
#define D_    128
#define DA_   64
#define DB_   8
#define NR_   6
#define NS_   42
#define E_MAX 200000
#define T_MAX 1600000
#define RT_MAX 12504            // row-tiles of 16

// ---------------- scratch (static device globals; no allocation) ------------
__device__ __align__(16) uint4 g_fX  [(size_t)2 * RT_MAX * 8 * 32];
__device__ __align__(16) float g_down[(size_t)E_MAX * DA_];
__device__ __align__(16) float g_agg [(size_t)E_MAX * DA_];
__device__ __align__(16) float g_wcomb[NR_ * D_];
__device__ __align__(16) float g_hsbf[(size_t)T_MAX * DB_];
__device__ __align__(16) uint32_t g_wfrag[163840];

#define OFF_Wkj    0
#define OFF_Wji    16384
#define OFF_rb1W1  32768
#define OFF_rb1W2  49152
#define OFF_Wfin   65536
#define OFF_ra1W1  81920
#define OFF_ra1W2  98304
#define OFF_ra2W1  114688
#define OFF_ra2W2  131072
#define OFF_Wdown  147456
#define OFF_Wup    155648

// ---------------- helpers ----------------------------------------------------
__device__ __forceinline__ float silu_f(float x) {
    return x / (1.0f + __expf(-x));
}
__device__ __forceinline__ void splitpack2(float x0, float x1,
                                           uint32_t& hi, uint32_t& lo) {
    asm("cvt.rn.bf16x2.f32 %0, %1, %2;" : "=r"(hi) : "f"(x1), "f"(x0));
    float f0 = __uint_as_float(hi << 16);
    float f1 = __uint_as_float(hi & 0xFFFF0000u);
    float l0 = x0 - f0;
    float l1 = x1 - f1;
    asm("cvt.rn.bf16x2.f32 %0, %1, %2;" : "=r"(lo) : "f"(l1), "f"(l0));
}
__device__ __forceinline__ float lo16f(uint32_t u) { return __uint_as_float(u << 16); }
__device__ __forceinline__ float hi16f(uint32_t u) { return __uint_as_float(u & 0xFFFF0000u); }

__device__ __forceinline__ void mma_bf16(float* c, const uint32_t* a, const uint32_t* b) {
    asm volatile(
        "mma.sync.aligned.m16n8k16.row.col.f32.bf16.bf16.f32 "
        "{%0,%1,%2,%3}, {%4,%5,%6,%7}, {%8,%9}, {%0,%1,%2,%3};"
        : "+f"(c[0]), "+f"(c[1]), "+f"(c[2]), "+f"(c[3])
        : "r"(a[0]), "r"(a[1]), "r"(a[2]), "r"(a[3]), "r"(b[0]), "r"(b[1]));
}
__device__ __forceinline__ void cp_async16(uint32_t saddr, const void* gaddr) {
    asm volatile("cp.async.cg.shared.global [%0], [%1], 16;"
                 :: "r"(saddr), "l"(gaddr));
}
#define CP_COMMIT() asm volatile("cp.async.commit_group;" ::: "memory")
#define CP_WAIT(n)  asm volatile("cp.async.wait_group %0;" :: "n"(n) : "memory")
__device__ __forceinline__ uint32_t smem_u32(const void* p) {
    uint32_t a;
    asm("{ .reg .u64 t; cvta.to.shared.u64 t, %1; cvt.u32.u64 %0, t; }" : "=r"(a) : "l"(p));
    return a;
}

// ---------------- fused HEAD chain: Wkj -> Wdown -> Wji, 64 rows/CTA -----------
#define HSM_BIAS 0                      // bkj[128], bji[128]
#define HSM_WC   1024                   // wcomb 6x128
#define HSM_M    4096                   // 32768: m_input frags
#define HSM_P    (HSM_M + 32768)        // 32768: Wkj output frags
#define HSM_BS   (HSM_P + 32768)        // 4 x 8192 B ring
#define HSM_TOTAL (HSM_BS + 32768)      // 102400

__global__ void __launch_bounds__(256, 2) head_chain(
    const float* __restrict__ m_input, const float* __restrict__ rbf,
    const uint32_t* __restrict__ wf,
    const float* __restrict__ bkj, const float* __restrict__ bji,
    const float* __restrict__ wcombG,
    float* __restrict__ down,
    uint4* __restrict__ fXH, uint4* __restrict__ fXL, int E)
{
    extern __shared__ char smem[];
    const uint32_t sb = smem_u32(smem);
    const int tid = threadIdx.x, lane = tid & 31, wid = tid >> 5;
    const int warpM = wid >> 2, warpN = wid & 3;
    const int rt0 = blockIdx.x * 4;                 // 64 rows per CTA

    if (tid < 128) {
        ((float*)(smem + HSM_BIAS))[tid]       = bkj[tid];
        ((float*)(smem + HSM_BIAS))[128 + tid] = bji[tid];
    }
    for (int i = tid; i < NR_ * D_; i += 256)
        ((float*)(smem + HSM_WC))[i] = wcombG[i];

    // ---- A preload + split (once) into M ----
#pragma unroll
    for (int i = 0; i < 4; i++) {
        int f = tid + i * 256;
        int ln = f & 31, gm = (f >> 5) & 3, s = f >> 7;
        int r0 = rt0 * 16 + gm * 16 + (ln >> 2);
        int k0 = s * 16 + 2 * (ln & 3);
        int rA = (r0     < E) ? r0     : E - 1;
        int rB = (r0 + 8 < E) ? r0 + 8 : E - 1;
        const float* bA = m_input + (size_t)rA * D_ + k0;
        const float* bB = m_input + (size_t)rB * D_ + k0;
        float2 v0 = *(const float2*)bA;
        float2 v1 = *(const float2*)bB;
        float2 v2 = *(const float2*)(bA + 8);
        float2 v3 = *(const float2*)(bB + 8);
        uint4 h, l;
        splitpack2(v0.x, v0.y, h.x, l.x);
        splitpack2(v1.x, v1.y, h.y, l.y);
        splitpack2(v2.x, v2.y, h.z, l.z);
        splitpack2(v3.x, v3.y, h.w, l.w);
        *(uint4*)(smem + HSM_M + (((s * 2 + 0) * 4 + gm) * 32 + ln) * 16) = h;
        *(uint4*)(smem + HSM_M + (((s * 2 + 1) * 4 + gm) * 32 + ln) * 16) = l;
    }

    float acc[2][4][4];

    auto prefB = [&](const uint32_t* wfb, int s, int nq4) {
#pragma unroll
        for (int i = 0; i < 2; i++) {
            int f = tid + i * 256;
            if (f < nq4)
                cp_async16(sb + HSM_BS + (s & 3) * 8192 + f * 16,
                           (const uint4*)wfb + s * nq4 + f);
        }
    };
    auto compute128 = [&](int aOff, int s) {
        const char* ab = smem + aOff;
        uint4 ahi[2], alo[2];
#pragma unroll
        for (int mt = 0; mt < 2; mt++) {
            int gm = warpM * 2 + mt;
            ahi[mt] = *(const uint4*)(ab + (((s * 2 + 0) * 4 + gm) * 32 + lane) * 16);
            alo[mt] = *(const uint4*)(ab + (((s * 2 + 1) * 4 + gm) * 32 + lane) * 16);
        }
#pragma unroll
        for (int nt = 0; nt < 4; nt++) {
            int gt = warpN * 4 + nt;
            uint4 bq = *(const uint4*)(smem + HSM_BS + (s & 3) * 8192 + (gt * 32 + lane) * 16);
            uint32_t bh[2] = {bq.x, bq.y};
            uint32_t bl[2] = {bq.z, bq.w};
#pragma unroll
            for (int mt = 0; mt < 2; mt++) {
                mma_bf16(acc[mt][nt], (const uint32_t*)&ahi[mt], bh);
                mma_bf16(acc[mt][nt], (const uint32_t*)&ahi[mt], bl);
                mma_bf16(acc[mt][nt], (const uint32_t*)&alo[mt], bh);
            }
        }
    };
    auto runstage128 = [&](int aOff, const uint32_t* wfb) {
#pragma unroll
        for (int mt = 0; mt < 2; mt++)
#pragma unroll
            for (int nt = 0; nt < 4; nt++)
#pragma unroll
                for (int j = 0; j < 4; j++) acc[mt][nt][j] = 0.f;
        prefB(wfb, 0, 512); CP_COMMIT();
        prefB(wfb, 1, 512); CP_COMMIT();
        for (int s = 0; s < 8; s++) {
            if (s + 2 < 8) { prefB(wfb, s + 2, 512); CP_COMMIT(); }
            if (s + 2 < 8)      CP_WAIT(2);
            else if (s + 1 < 8) CP_WAIT(1);
            else                CP_WAIT(0);
            __syncthreads();
            compute128(aOff, s);
        }
    };

    // ================= S0: Wkj (A=M) -> P, epi silu(+bkj) * rbfmod ============
    runstage128(HSM_M, wf + OFF_Wkj);
    {
        float* sBk = (float*)(smem + HSM_BIAS);
        float* sWc = (float*)(smem + HSM_WC);
#pragma unroll
        for (int mt = 0; mt < 2; mt++) {
            const int rtg = rt0 + warpM * 2 + mt;
            const int gm  = warpM * 2 + mt;
            float o[4][4];
#pragma unroll
            for (int nt = 0; nt < 4; nt++) {
                int col = warpN * 32 + nt * 8 + 2 * (lane & 3);
#pragma unroll
                for (int half = 0; half < 2; half++) {
                    o[nt][half * 2 + 0] = silu_f(acc[mt][nt][half * 2 + 0] + sBk[col]);
                    o[nt][half * 2 + 1] = silu_f(acc[mt][nt][half * 2 + 1] + sBk[col + 1]);
                }
            }
            int rA = rtg * 16 + (lane >> 2);
            int rB = rA + 8;
            if (rA >= E) rA = E - 1;
            if (rB >= E) rB = E - 1;
            const float* pa = rbf + (size_t)rA * NR_;
            const float* pb = rbf + (size_t)rB * NR_;
            float2 a0 = __ldg((const float2*)pa), a1 = __ldg((const float2*)pa + 1),
                   a2 = __ldg((const float2*)pa + 2);
            float2 b0 = __ldg((const float2*)pb), b1 = __ldg((const float2*)pb + 1),
                   b2 = __ldg((const float2*)pb + 2);
            float hA[6] = {a0.x, a0.y, a1.x, a1.y, a2.x, a2.y};
            float hB[6] = {b0.x, b0.y, b1.x, b1.y, b2.x, b2.y};
#pragma unroll
            for (int nt = 0; nt < 4; nt++) {
                int col = warpN * 32 + nt * 8 + 2 * (lane & 3);
                float r0 = 0.f, r1 = 0.f, r2 = 0.f, r3 = 0.f;
#pragma unroll
                for (int j = 0; j < NR_; j++) {
                    float w0 = sWc[j * D_ + col], w1 = sWc[j * D_ + col + 1];
                    r0 += hA[j] * w0; r1 += hA[j] * w1;
                    r2 += hB[j] * w0; r3 += hB[j] * w1;
                }
                o[nt][0] *= r0; o[nt][1] *= r1; o[nt][2] *= r2; o[nt][3] *= r3;
            }
#pragma unroll
            for (int j = 0; j < 2; j++) {
                uint4 h, l;
                splitpack2(o[2 * j][0],     o[2 * j][1],     h.x, l.x);
                splitpack2(o[2 * j][2],     o[2 * j][3],     h.y, l.y);
                splitpack2(o[2 * j + 1][0], o[2 * j + 1][1], h.z, l.z);
                splitpack2(o[2 * j + 1][2], o[2 * j + 1][3], h.w, l.w);
                int sp = warpN * 2 + j;
                *(uint4*)(smem + HSM_P + (((sp * 2 + 0) * 4 + gm) * 32 + lane) * 16) = h;
                *(uint4*)(smem + HSM_P + (((sp * 2 + 1) * 4 + gm) * 32 + lane) * 16) = l;
            }
        }
    }

    // ================= S1: Wdown (A=P, NT=64) -> down fp32 global =============
    {
        const int gm4 = wid >> 1;       // 0..3 (16 rows each)
        const int wn2 = wid & 1;        // 0..1 (32 cols each)
        float a1acc[4][4];
#pragma unroll
        for (int nt = 0; nt < 4; nt++)
#pragma unroll
            for (int j = 0; j < 4; j++) a1acc[nt][j] = 0.f;
        const uint32_t* wfb = wf + OFF_Wdown;
        prefB(wfb, 0, 256); CP_COMMIT();
        prefB(wfb, 1, 256); CP_COMMIT();
        for (int s = 0; s < 8; s++) {
            if (s + 2 < 8) { prefB(wfb, s + 2, 256); CP_COMMIT(); }
            if (s + 2 < 8)      CP_WAIT(2);
            else if (s + 1 < 8) CP_WAIT(1);
            else                CP_WAIT(0);
            __syncthreads();
            const char* ab = smem + HSM_P;
            uint4 ahi = *(const uint4*)(ab + (((s * 2 + 0) * 4 + gm4) * 32 + lane) * 16);
            uint4 alo = *(const uint4*)(ab + (((s * 2 + 1) * 4 + gm4) * 32 + lane) * 16);
#pragma unroll
            for (int nt = 0; nt < 4; nt++) {
                int gt = wn2 * 4 + nt;
                uint4 bq = *(const uint4*)(smem + HSM_BS + (s & 3) * 8192 + (gt * 32 + lane) * 16);
                uint32_t bh[2] = {bq.x, bq.y};
                uint32_t bl[2] = {bq.z, bq.w};
                mma_bf16(a1acc[nt], (const uint32_t*)&ahi, bh);
                mma_bf16(a1acc[nt], (const uint32_t*)&ahi, bl);
                mma_bf16(a1acc[nt], (const uint32_t*)&alo, bh);
            }
        }
        const int rtg = rt0 + gm4;
#pragma unroll
        for (int nt = 0; nt < 4; nt++) {
            int col = wn2 * 32 + nt * 8 + 2 * (lane & 3);
#pragma unroll
            for (int half = 0; half < 2; half++) {
                int row = rtg * 16 + (lane >> 2) + half * 8;
                if (row < E)
                    *(float2*)(down + (size_t)row * DA_ + col) =
                        make_float2(silu_f(a1acc[nt][half * 2 + 0]),
                                    silu_f(a1acc[nt][half * 2 + 1]));
            }
        }
    }

    // ================= S2: Wji (A=M) -> fX frag global, epi silu(+bji) ========
    runstage128(HSM_M, wf + OFF_Wji);
    {
        float* sBj = (float*)(smem + HSM_BIAS) + 128;
#pragma unroll
        for (int mt = 0; mt < 2; mt++) {
            const int rtg = rt0 + warpM * 2 + mt;
            float o[4][4];
#pragma unroll
            for (int nt = 0; nt < 4; nt++) {
                int col = warpN * 32 + nt * 8 + 2 * (lane & 3);
#pragma unroll
                for (int half = 0; half < 2; half++) {
                    o[nt][half * 2 + 0] = silu_f(acc[mt][nt][half * 2 + 0] + sBj[col]);
                    o[nt][half * 2 + 1] = silu_f(acc[mt][nt][half * 2 + 1] + sBj[col + 1]);
                }
            }
#pragma unroll
            for (int j = 0; j < 2; j++) {
                uint4 h, l;
                splitpack2(o[2 * j][0],     o[2 * j][1],     h.x, l.x);
                splitpack2(o[2 * j][2],     o[2 * j][3],     h.y, l.y);
                splitpack2(o[2 * j + 1][0], o[2 * j + 1][1], h.z, l.z);
                splitpack2(o[2 * j + 1][2], o[2 * j + 1][3], h.w, l.w);
                int q = (rtg * 8 + warpN * 2 + j) * 32 + lane;
                fXH[q] = h;
                fXL[q] = l;
            }
        }
    }
}

// ---------------- fused 8-GEMM TAIL chain (validated R14: 4-slab, 1 step/sync) -
#define RES_NONE 0
#define RES_SMEM 1
#define RES_GFR  2
#define RES_F32  3

#define TSM_BIAS 0
#define TSM_P    4096
#define TSM_Q    (TSM_P + 32768)
#define TSM_BS   (TSM_Q + 32768)
#define TSM_TOTAL (TSM_BS + 32768)     // 102400

template<int RES, bool OUTG>
__device__ __forceinline__ void epi_stage64(
    char* smem, float (&acc)[2][4][4], const float* sBiasG,
    int resOff, const uint4* gResH, const uint4* gResL, const float* resF,
    int outOff, float* outF,
    int lane, int warpM, int warpN, int rt0, int E)
{
#pragma unroll
    for (int mt = 0; mt < 2; mt++) {
        const int rtg = rt0 + warpM * 2 + mt;
        const int gm  = warpM * 2 + mt;
        float o[4][4];
#pragma unroll
        for (int nt = 0; nt < 4; nt++) {
            int col = warpN * 32 + nt * 8 + 2 * (lane & 3);
            float b0 = sBiasG ? sBiasG[col]     : 0.f;
            float b1 = sBiasG ? sBiasG[col + 1] : 0.f;
#pragma unroll
            for (int half = 0; half < 2; half++) {
                o[nt][half * 2 + 0] = silu_f(acc[mt][nt][half * 2 + 0] + b0);
                o[nt][half * 2 + 1] = silu_f(acc[mt][nt][half * 2 + 1] + b1);
            }
        }
        if (RES == RES_SMEM || RES == RES_GFR) {
#pragma unroll
            for (int j = 0; j < 2; j++) {
                uint4 rh, rl;
                int sp = warpN * 2 + j;
                if (RES == RES_SMEM) {
                    rh = *(const uint4*)(smem + resOff + (((sp * 2 + 0) * 4 + gm) * 32 + lane) * 16);
                    rl = *(const uint4*)(smem + resOff + (((sp * 2 + 1) * 4 + gm) * 32 + lane) * 16);
                } else {
                    int q = (rtg * 8 + sp) * 32 + lane;
                    rh = __ldg(gResH + q);
                    rl = __ldg(gResL + q);
                }
                o[2 * j    ][0] += lo16f(rh.x) + lo16f(rl.x);
                o[2 * j    ][1] += hi16f(rh.x) + hi16f(rl.x);
                o[2 * j    ][2] += lo16f(rh.y) + lo16f(rl.y);
                o[2 * j    ][3] += hi16f(rh.y) + hi16f(rl.y);
                o[2 * j + 1][0] += lo16f(rh.z) + lo16f(rl.z);
                o[2 * j + 1][1] += hi16f(rh.z) + hi16f(rl.z);
                o[2 * j + 1][2] += lo16f(rh.w) + lo16f(rl.w);
                o[2 * j + 1][3] += hi16f(rh.w) + hi16f(rl.w);
            }
        } else if (RES == RES_F32) {
#pragma unroll
            for (int nt = 0; nt < 4; nt++) {
                int col = warpN * 32 + nt * 8 + 2 * (lane & 3);
#pragma unroll
                for (int half = 0; half < 2; half++) {
                    int row = rtg * 16 + (lane >> 2) + half * 8;
                    if (row >= E) row = E - 1;
                    float2 rr = __ldg((const float2*)(resF + (size_t)row * D_ + col));
                    o[nt][half * 2 + 0] += rr.x;
                    o[nt][half * 2 + 1] += rr.y;
                }
            }
        }
        if (OUTG) {
#pragma unroll
            for (int nt = 0; nt < 4; nt++) {
                int col = warpN * 32 + nt * 8 + 2 * (lane & 3);
#pragma unroll
                for (int half = 0; half < 2; half++) {
                    int row = rtg * 16 + (lane >> 2) + half * 8;
                    if (row < E)
                        *(float2*)(outF + (size_t)row * D_ + col) =
                            make_float2(o[nt][half * 2], o[nt][half * 2 + 1]);
                }
            }
        } else {
#pragma unroll
            for (int j = 0; j < 2; j++) {
                uint4 h, l;
                splitpack2(o[2 * j][0],     o[2 * j][1],     h.x, l.x);
                splitpack2(o[2 * j][2],     o[2 * j][3],     h.y, l.y);
                splitpack2(o[2 * j + 1][0], o[2 * j + 1][1], h.z, l.z);
                splitpack2(o[2 * j + 1][2], o[2 * j + 1][3], h.w, l.w);
                int sp = warpN * 2 + j;
                *(uint4*)(smem + outOff + (((sp * 2 + 0) * 4 + gm) * 32 + lane) * 16) = h;
                *(uint4*)(smem + outOff + (((sp * 2 + 1) * 4 + gm) * 32 + lane) * 16) = l;
            }
        }
    }
}

__global__ void __launch_bounds__(256, 2) tail_chain(
    const float* __restrict__ agg,
    const uint4* __restrict__ fXH,   const uint4* __restrict__ fXL,
    const float* __restrict__ m_input,
    const uint32_t* __restrict__ wf,
    const float* b_rb1b1, const float* b_rb1b2, const float* b_fin,
    const float* b_ra1b1, const float* b_ra1b2,
    const float* b_ra2b1, const float* b_ra2b2,
    float* __restrict__ outp, int E)
{
    extern __shared__ char smem[];
    const uint32_t sb = smem_u32(smem);
    const int tid = threadIdx.x, lane = tid & 31, wid = tid >> 5;
    const int warpM = wid >> 2, warpN = wid & 3;
    const int rt0 = blockIdx.x * 4;

    {
        const float* bs[7] = {b_rb1b1, b_rb1b2, b_fin, b_ra1b1, b_ra1b2, b_ra2b1, b_ra2b2};
        if (tid < 128)
#pragma unroll
            for (int g = 0; g < 7; g++)
                ((float*)(smem + TSM_BIAS))[g * 128 + tid] = bs[g][tid];
    }
    float* sB = (float*)(smem + TSM_BIAS);

    // stage-0 A: load agg fp32 + split directly into Q (replaces k_asplit)
    {
#pragma unroll
        for (int i = 0; i < 2; i++) {
            int f2 = tid + i * 256;
            int ln = f2 & 31, gm = (f2 >> 5) & 3, s = f2 >> 7;
            int r0 = (rt0 + gm) * 16 + (ln >> 2);
            int k0 = s * 16 + 2 * (ln & 3);
            const float* bA = agg + (size_t)r0 * DA_ + k0;
            const float* bB = bA + (size_t)8 * DA_;
            float2 v0 = *(const float2*)bA;
            float2 v1 = *(const float2*)bB;
            float2 v2 = *(const float2*)(bA + 8);
            float2 v3 = *(const float2*)(bB + 8);
            uint4 h, l;
            splitpack2(v0.x, v0.y, h.x, l.x);
            splitpack2(v1.x, v1.y, h.y, l.y);
            splitpack2(v2.x, v2.y, h.z, l.z);
            splitpack2(v3.x, v3.y, h.w, l.w);
            *(uint4*)(smem + TSM_Q + (((s * 2 + 0) * 4 + gm) * 32 + ln) * 16) = h;
            *(uint4*)(smem + TSM_Q + (((s * 2 + 1) * 4 + gm) * 32 + ln) * 16) = l;
        }
    }

    float acc[2][4][4];

    auto prefB = [&](const uint32_t* wfb, int s) {
#pragma unroll
        for (int i = 0; i < 2; i++) {
            int f = tid + i * 256;
            cp_async16(sb + TSM_BS + (s & 3) * 8192 + f * 16,
                       (const uint4*)wfb + s * 512 + f);
        }
    };
    auto compute = [&](int aOff, int s) {
        const char* ab = smem + aOff;
        uint4 ahi[2], alo[2];
#pragma unroll
        for (int mt = 0; mt < 2; mt++) {
            int gm = warpM * 2 + mt;
            ahi[mt] = *(const uint4*)(ab + (((s * 2 + 0) * 4 + gm) * 32 + lane) * 16);
            alo[mt] = *(const uint4*)(ab + (((s * 2 + 1) * 4 + gm) * 32 + lane) * 16);
        }
#pragma unroll
        for (int nt = 0; nt < 4; nt++) {
            int gt = warpN * 4 + nt;
            uint4 bq = *(const uint4*)(smem + TSM_BS + (s & 3) * 8192 + (gt * 32 + lane) * 16);
            uint32_t bh[2] = {bq.x, bq.y};
            uint32_t bl[2] = {bq.z, bq.w};
#pragma unroll
            for (int mt = 0; mt < 2; mt++) {
                mma_bf16(acc[mt][nt], (const uint32_t*)&ahi[mt], bh);
                mma_bf16(acc[mt][nt], (const uint32_t*)&ahi[mt], bl);
                mma_bf16(acc[mt][nt], (const uint32_t*)&alo[mt], bh);
            }
        }
    };
    auto runstage = [&](int aOff, const uint32_t* wfb, int KT) {
#pragma unroll
        for (int mt = 0; mt < 2; mt++)
#pragma unroll
            for (int nt = 0; nt < 4; nt++)
#pragma unroll
                for (int j = 0; j < 4; j++) acc[mt][nt][j] = 0.f;
        prefB(wfb, 0); CP_COMMIT();
        prefB(wfb, 1); CP_COMMIT();
        for (int s = 0; s < KT; s++) {
            if (s + 2 < KT) { prefB(wfb, s + 2); CP_COMMIT(); }
            if (s + 2 < KT)      CP_WAIT(2);
            else if (s + 1 < KT) CP_WAIT(1);
            else                 CP_WAIT(0);
            __syncthreads();
            compute(aOff, s);
        }
    };

    runstage(TSM_Q, wf + OFF_Wup, 4);
    epi_stage64<RES_GFR, false>(smem, acc, nullptr, 0, fXH, fXL, nullptr,
                                TSM_P, nullptr, lane, warpM, warpN, rt0, E);
    runstage(TSM_P, wf + OFF_rb1W1, 8);
    epi_stage64<RES_NONE, false>(smem, acc, sB + 0 * 128, 0, nullptr, nullptr, nullptr,
                                 TSM_Q, nullptr, lane, warpM, warpN, rt0, E);
    runstage(TSM_Q, wf + OFF_rb1W2, 8);
    epi_stage64<RES_SMEM, false>(smem, acc, sB + 1 * 128, TSM_P, nullptr, nullptr, nullptr,
                                 TSM_P, nullptr, lane, warpM, warpN, rt0, E);
    runstage(TSM_P, wf + OFF_Wfin, 8);
    epi_stage64<RES_F32, false>(smem, acc, sB + 2 * 128, 0, nullptr, nullptr, m_input,
                                TSM_Q, nullptr, lane, warpM, warpN, rt0, E);
    runstage(TSM_Q, wf + OFF_ra1W1, 8);
    epi_stage64<RES_NONE, false>(smem, acc, sB + 3 * 128, 0, nullptr, nullptr, nullptr,
                                 TSM_P, nullptr, lane, warpM, warpN, rt0, E);
    runstage(TSM_P, wf + OFF_ra1W2, 8);
    epi_stage64<RES_SMEM, false>(smem, acc, sB + 4 * 128, TSM_Q, nullptr, nullptr, nullptr,
                                 TSM_Q, nullptr, lane, warpM, warpN, rt0, E);
    runstage(TSM_Q, wf + OFF_ra2W1, 8);
    epi_stage64<RES_NONE, false>(smem, acc, sB + 5 * 128, 0, nullptr, nullptr, nullptr,
                                 TSM_P, nullptr, lane, warpM, warpN, rt0, E);
    runstage(TSM_P, wf + OFF_ra2W2, 8);
    epi_stage64<RES_SMEM, true>(smem, acc, sB + 6 * 128, TSM_Q, nullptr, nullptr, nullptr,
                                0, outp, lane, warpM, warpN, rt0, E);
}

// ---------------- merged weight fragment prep (+wcomb) -------------------------
__global__ void __launch_bounds__(256) k_wfrag_all(
    const float* w0, const float* w1, const float* w2, const float* w3,
    const float* w4, const float* w5, const float* w6, const float* w7,
    const float* w8, const float* w9, const float* w10,
    const float* wrbf1, const float* wrbf2, float* wcomb,
    uint32_t* __restrict__ outv)
{
    int b = blockIdx.x;
    if (b >= 160) {
        int idx = (b - 160) * 256 + threadIdx.x;
        if (idx >= NR_ * D_) return;
        int j = idx / D_, n = idx % D_;
        float s = 0.f;
#pragma unroll
        for (int k = 0; k < DB_; k++) s += wrbf1[j * DB_ + k] * wrbf2[k * D_ + n];
        wcomb[idx] = s;
        return;
    }
    const float* Ws[11] = {w0, w1, w2, w3, w4, w5, w6, w7, w8, w9, w10};
    const float* W;
    int K, N, off, lidx;
    if (b < 144) {
        int w = b / 16;
        W = Ws[w]; K = 128; N = 128;
        off = w * 16384;
        lidx = (b % 16) * 256 + threadIdx.x;
    } else if (b < 152) {
        W = Ws[9]; K = 128; N = 64; off = OFF_Wdown;
        lidx = (b - 144) * 256 + threadIdx.x;
    } else {
        W = Ws[10]; K = 64; N = 128; off = OFF_Wup;
        lidx = (b - 152) * 256 + threadIdx.x;
    }
    int total = (K / 16) * (N / 8) * 32;
    if (lidx >= total) return;
    int lane = lidx & 31;
    int st   = lidx >> 5;
    int t    = st % (N / 8);
    int s    = st / (N / 8);
    int q = lane & 3, r = lane >> 2;
    int n  = t * 8 + r;
    int k0 = s * 16 + 2 * q;
    float a00 = __ldg(W + (size_t)k0 * N + n);
    float a01 = __ldg(W + (size_t)(k0 + 1) * N + n);
    float a10 = __ldg(W + (size_t)(k0 + 8) * N + n);
    float a11 = __ldg(W + (size_t)(k0 + 9) * N + n);
    uint32_t h0, l0, h1, l1;
    splitpack2(a00, a01, h0, l0);
    splitpack2(a10, a11, h1, l1);
    ((uint4*)(outv + off))[lidx] = make_uint4(h0, h1, l0, l1);
}

// ---------------- small kernels -------------------------------------------------
__global__ void __launch_bounds__(256) k_zero(float4* __restrict__ p, int n4) {
    int i = blockIdx.x * blockDim.x + threadIdx.x;
    if (i < n4) p[i] = make_float4(0.f, 0.f, 0.f, 0.f);
}

__global__ void __launch_bounds__(256) k_hsbf(
    const float* __restrict__ sbf, const float* __restrict__ w1,
    float* __restrict__ out, int T)
{
    __shared__ float st[256 * NS_];
    __shared__ float sw[NS_ * DB_];
    for (int i = threadIdx.x; i < NS_ * DB_; i += 256) sw[i] = w1[i];

    int base = blockIdx.x * 256;
    int n = T - base; if (n > 256) n = 256;
    int total = n * NS_;
    int t4 = total >> 2;
    const float4* s4 = (const float4*)(sbf + (size_t)base * NS_);
    for (int i = threadIdx.x; i < t4; i += 256)
        ((float4*)st)[i] = __ldg(s4 + i);
    for (int i = t4 * 4 + threadIdx.x; i < total; i += 256)
        st[i] = sbf[(size_t)base * NS_ + i];
    __syncthreads();

    int r = threadIdx.x;
    if (r >= n) return;
    const float* x = &st[r * NS_];
    float h[DB_];
#pragma unroll
    for (int k = 0; k < DB_; k++) h[k] = 0.f;
#pragma unroll
    for (int j = 0; j < NS_; j++) {
        float xv = x[j];
#pragma unroll
        for (int k = 0; k < DB_; k++) h[k] += xv * sw[j * DB_ + k];
    }
    float4* op = (float4*)(out + (size_t)(base + r) * DB_);
    op[0] = make_float4(h[0], h[1], h[2], h[3]);
    op[1] = make_float4(h[4], h[5], h[6], h[7]);
}

// Triplet scatter with software-pipelined index/hsbf prefetch (math unchanged).
__global__ void __launch_bounds__(256) k_triplet(
    const float* __restrict__ hsbf, const float* __restrict__ wsbf2,
    const int* __restrict__ exp_kj, const int* __restrict__ red_ji,
    const float* __restrict__ down, float* __restrict__ agg, int T)
{
    __shared__ float sw[DB_ * DA_];
    for (int i = threadIdx.x; i < DB_ * DA_; i += 256) sw[i] = wsbf2[i];
    __syncthreads();

    const int q = threadIdx.x & 15;
    float w[DB_][4];
#pragma unroll
    for (int i = 0; i < DB_; i++)
#pragma unroll
        for (int j = 0; j < 4; j++) w[i][j] = sw[i * DA_ + q * 4 + j];

    int t = (blockIdx.x * blockDim.x + threadIdx.x) >> 4;
    const int stride = (gridDim.x * blockDim.x) >> 4;
    if (t >= T) return;

    // prefetch iteration 0
    int e = __ldg(exp_kj + t);
    int g = __ldg(red_ji + t);
    const float4* hp = (const float4*)(hsbf + (size_t)t * DB_);
    float4 h0 = __ldg(hp), h1 = __ldg(hp + 1);

    while (true) {
        const int tn = t + stride;
        const bool has = (tn < T);
        int e2 = 0, g2 = 0;
        float4 h0n = make_float4(0.f, 0.f, 0.f, 0.f), h1n = h0n;
        if (has) {
            e2 = __ldg(exp_kj + tn);
            g2 = __ldg(red_ji + tn);
            const float4* hpn = (const float4*)(hsbf + (size_t)tn * DB_);
            h0n = __ldg(hpn);
            h1n = __ldg(hpn + 1);
        }

        // gather can issue immediately — e arrived last iteration
        float4 a = __ldg((const float4*)(down + (size_t)e * DA_ + q * 4));

        float hh[8] = {h0.x, h0.y, h0.z, h0.w, h1.x, h1.y, h1.z, h1.w};
        float s0 = 0.f, s1 = 0.f, s2 = 0.f, s3 = 0.f;
#pragma unroll
        for (int i = 0; i < DB_; i++) {
            s0 += hh[i] * w[i][0];
            s1 += hh[i] * w[i][1];
            s2 += hh[i] * w[i][2];
            s3 += hh[i] * w[i][3];
        }
        float vx = a.x * s0, vy = a.y * s1, vz = a.z * s2, vw = a.w * s3;

        float* dst = agg + (size_t)g * DA_ + q * 4;
        asm volatile("red.global.add.v4.f32 [%0], {%1, %2, %3, %4};"
                     :: "l"(dst), "f"(vx), "f"(vy), "f"(vz), "f"(vw)
                     : "memory");

        if (!has) break;
        t = tn; e = e2; g = g2; h0 = h0n; h1 = h1n;
    }
}

// ---------------- launch -------------------------------------------------------
extern "C" void kernel_launch(void* const* d_in, const int* in_sizes, int n_in,
                              void* d_out, int out_size)
{
    const float* m_input  = (const float*)d_in[0];
    const float* rbf      = (const float*)d_in[1];
    const float* sbf      = (const float*)d_in[2];
    const float* Wkj      = (const float*)d_in[3];
    const float* bkj      = (const float*)d_in[4];
    const float* Wrbf1    = (const float*)d_in[5];
    const float* Wrbf2    = (const float*)d_in[6];
    const float* Wdown    = (const float*)d_in[7];
    const float* Wsbf1    = (const float*)d_in[8];
    const float* Wsbf2    = (const float*)d_in[9];
    const float* Wup      = (const float*)d_in[10];
    const float* Wji      = (const float*)d_in[11];
    const float* bji      = (const float*)d_in[12];
    const float* rb1_W1   = (const float*)d_in[13];
    const float* rb1_b1   = (const float*)d_in[14];
    const float* rb1_W2   = (const float*)d_in[15];
    const float* rb1_b2   = (const float*)d_in[16];
    const float* Wfin     = (const float*)d_in[17];
    const float* bfin     = (const float*)d_in[18];
    const float* ra1_W1   = (const float*)d_in[19];
    const float* ra1_b1   = (const float*)d_in[20];
    const float* ra1_W2   = (const float*)d_in[21];
    const float* ra1_b2   = (const float*)d_in[22];
    const float* ra2_W1   = (const float*)d_in[23];
    const float* ra2_b1   = (const float*)d_in[24];
    const float* ra2_W2   = (const float*)d_in[25];
    const float* ra2_b2   = (const float*)d_in[26];
    const int*   red_ji   = (const int*)  d_in[27];
    const int*   exp_kj   = (const int*)  d_in[28];

    const int E = in_sizes[0] / D_;
    const int T = in_sizes[27];

    uint4 *fX;
    float *down, *agg, *wcomb, *hsbf;
    uint32_t *wf;
    cudaGetSymbolAddress((void**)&fX,   g_fX);
    cudaGetSymbolAddress((void**)&down, g_down);
    cudaGetSymbolAddress((void**)&agg,  g_agg);
    cudaGetSymbolAddress((void**)&wcomb, g_wcomb);
    cudaGetSymbolAddress((void**)&hsbf, g_hsbf);
    cudaGetSymbolAddress((void**)&wf,   g_wfrag);

    const size_t P8 = (size_t)RT_MAX * 8 * 32;

    float* outp = (float*)d_out;
    const int grid64 = (E + 63) / 64;

    cudaFuncSetAttribute((const void*)head_chain, cudaFuncAttributeMaxDynamicSharedMemorySize, HSM_TOTAL);
    cudaFuncSetAttribute((const void*)tail_chain, cudaFuncAttributeMaxDynamicSharedMemorySize, TSM_TOTAL);

    cudaStream_t s2;
    cudaStreamCreateWithFlags(&s2, cudaStreamNonBlocking);
    cudaEvent_t evFork, evJoin;
    cudaEventCreateWithFlags(&evFork, cudaEventDisableTiming);
    cudaEventCreateWithFlags(&evJoin, cudaEventDisableTiming);

    // fork: s2 runs {zero(agg), hsbf} under the head chain
    cudaEventRecord(evFork, 0);
    cudaStreamWaitEvent(s2, evFork, 0);
    {
        int n4 = (E * DA_) / 4;
        k_zero<<<(n4 + 255) / 256, 256, 0, s2>>>((float4*)agg, n4);
    }
    k_hsbf<<<(T + 255) / 256, 256, 0, s2>>>(sbf, Wsbf1, hsbf, T);
    cudaEventRecord(evJoin, s2);

    // main: weight prep, then fused head (Wkj -> Wdown -> Wji)
    k_wfrag_all<<<163, 256>>>(Wkj, Wji, rb1_W1, rb1_W2, Wfin,
                              ra1_W1, ra1_W2, ra2_W1, ra2_W2, Wdown, Wup,
                              Wrbf1, Wrbf2, wcomb, wf);
    head_chain<<<grid64, 256, HSM_TOTAL>>>(
        m_input, rbf, wf, bkj, bji, wcomb,
        down, fX, fX + P8, E);

    // join: triplet needs hsbf + zeroed agg
    cudaStreamWaitEvent(0, evJoin, 0);

    // triplet -> agg (software-pipelined)
    k_triplet<<<2048, 256>>>(hsbf, Wsbf2, exp_kj, red_ji, down, agg, T);

    // fused tail (agg split in prologue): Wup(+fJi) -> rb1 -> Wfin(+m_input)
    // -> ra1 -> ra2 -> out
    tail_chain<<<grid64, 256, TSM_TOTAL>>>(
        agg, fX, fX + P8, m_input, wf,
        rb1_b1, rb1_b2, bfin, ra1_b1, ra1_b2, ra2_b1, ra2_b2,
        outp, E);

    cudaEventDestroy(evFork);
    cudaEventDestroy(evJoin);
    cudaStreamDestroy(s2);
}